// round 13
// baseline (speedup 1.0000x reference)
#include <cuda_runtime.h>
#include <cuda_bf16.h>
#include <math.h>

#define NN 32768
#define EE 131072
#define BB 8
#define FIN 1025
#define KP1 1056        // K padded (multiple of 32)
#define CC 512
#define ND 1024
#define TS (1<<18)
#define ROUNDS 96
#define MBLK 148
#define SB_THRESH 12288

// ---------------- device scratch (static, no allocs) ----------------
__device__ float d_a[NN], d_b[NN];
__device__ float d_e[EE], d_ex[EE], d_score[EE];
__device__ unsigned d_m[NN];
__device__ float d_sum[NN];
__device__ unsigned long long d_key[EE];
__device__ int d_used[NN];
__device__ unsigned long long d_best[2][NN];
__device__ int d_list[2][EE];
__device__ int d_lcnt[2];
__device__ unsigned g_arrive;
__device__ int d_cluster[NN];
__device__ float d_nscore[NN];
__device__ int d_addsrc[NN];
__device__ unsigned d_table[TS];
__device__ int d_M;
__device__ int d_cu[EE], d_cv[EE];       // compact indices
__device__ float d_deg[NN], d_dis[NN];   // compact indexed
__device__ int d_indeg[NN];              // compact indexed
__device__ int d_off[NN + 1];
__device__ int d_fill[NN];
__device__ int d_adj[EE];
__device__ int d_nvalid, d_nvalid_pad;
__device__ int d_cmap[NN];               // node -> compact
__device__ int d_nodes[NN];              // compact -> node

__device__ __nv_bfloat16 d_Ah[(size_t)NN * KP1];
__device__ __nv_bfloat16 d_Al[(size_t)NN * KP1];
__device__ __nv_bfloat16 d_W1h[(size_t)ND * KP1];
__device__ __nv_bfloat16 d_W1l[(size_t)ND * KP1];
__device__ __nv_bfloat16 d_W2h[(size_t)ND * CC];
__device__ __nv_bfloat16 d_W2l[(size_t)ND * CC];
__device__ __nv_bfloat16 d_H1h[(size_t)NN * CC];
__device__ __nv_bfloat16 d_H1l[(size_t)NN * CC];
__device__ float d_Y[(size_t)NN * ND];
__device__ float d_H2[(size_t)NN * CC];
__device__ float d_gmax[BB * CC], d_gsum[BB * CC], d_cnt[BB];

__device__ __forceinline__ unsigned fenc(float f) {
    unsigned u = __float_as_uint(f);
    return (u & 0x80000000u) ? ~u : (u | 0x80000000u);
}
__device__ __forceinline__ float fdec(unsigned u) {
    return (u & 0x80000000u) ? __uint_as_float(u ^ 0x80000000u)
                             : __uint_as_float(~u);
}
__device__ __forceinline__ void bf16split(float v, __nv_bfloat16* hi, __nv_bfloat16* lo) {
    __nv_bfloat16 h = __float2bfloat16(v);
    *hi = h;
    *lo = __float2bfloat16(v - __bfloat162float(h));
}

// ---------------- init ----------------
__global__ void k_init() {
    int i = blockIdx.x * blockDim.x + threadIdx.x;
    if (i < TS) d_table[i] = 0xFFFFFFFFu;
    if (i < NN) {
        d_m[i] = 0u; d_sum[i] = 0.f; d_used[i] = 0;
        d_cluster[i] = i; d_nscore[i] = 1.f; d_addsrc[i] = -1;
        d_deg[i] = 0.f; d_indeg[i] = 0;
        d_best[0][i] = ~0ull; d_best[1][i] = ~0ull;
    }
    if (i < BB * CC) { d_gmax[i] = 0.f; d_gsum[i] = 0.f; }
    if (i < BB) d_cnt[i] = 0.f;
    if (i == 0) { d_M = 0; g_arrive = 0u; d_lcnt[0] = 0; d_lcnt[1] = 0; }
}

// pack weights TRANSPOSED [n][k] + split hi/lo
__global__ void k_packw1(const float* __restrict__ w0, const float* __restrict__ w1) {
    int idx = blockIdx.x * blockDim.x + threadIdx.x;
    if (idx >= ND * KP1) return;
    int n = idx / KP1, k = idx % KP1;
    float v = 0.f;
    if (k < FIN) v = (n < CC) ? w0[k * CC + n] : w1[k * CC + (n - CC)];
    bf16split(v, &d_W1h[idx], &d_W1l[idx]);
}
__global__ void k_packw2(const float* __restrict__ w0, const float* __restrict__ w1) {
    int idx = blockIdx.x * blockDim.x + threadIdx.x;
    if (idx >= ND * CC) return;
    int n = idx / CC, k = idx % CC;
    float v = (n < CC) ? w0[k * CC + n] : w1[k * CC + (n - CC)];
    bf16split(v, &d_W2h[idx], &d_W2l[idx]);
}

__global__ void k_node_dots(const float* __restrict__ x, const float* __restrict__ pw) {
    int n = blockIdx.x * (blockDim.x / 32) + (threadIdx.x >> 5);
    if (n >= NN) return;
    int lane = threadIdx.x & 31;
    const float* xr = x + (size_t)n * FIN;
    float sa = 0.f, sb = 0.f;
    for (int f = lane; f < FIN; f += 32) {
        float xv = xr[f];
        sa += xv * pw[f];
        sb += xv * pw[FIN + f];
    }
    for (int o = 16; o; o >>= 1) {
        sa += __shfl_down_sync(0xFFFFFFFFu, sa, o);
        sb += __shfl_down_sync(0xFFFFFFFFu, sb, o);
    }
    if (!lane) { d_a[n] = sa; d_b[n] = sb; }
}

// ---------------- persistent matching (softmax + frontier rounds) --------
__device__ __forceinline__ void gridbar(unsigned nb, unsigned* gen) {
    __syncthreads();
    if (threadIdx.x == 0) {
        __threadfence();
        atomicAdd(&g_arrive, 1u);
        unsigned target = (*gen) * nb;
        while (*((volatile unsigned*)&g_arrive) < target) __nanosleep(32);
    }
    __syncthreads();
}

// block-0-only tail rounds once frontier is small
__device__ void sb_tail(const int* __restrict__ ei, int r0) {
    const int t = threadIdx.x;
    const int lane = t & 31;
    for (int r = r0; r < ROUNDS; r++) {
        int p = r & 1;
        int total = *((volatile int*)&d_lcnt[p ^ 1]);
        if (total == 0) return;
        const int* src = d_list[p ^ 1];
        int* dst = d_list[p];
        // reset only touched best entries (only frontier endpoints are read)
        for (int i = t; i < total; i += 256) {
            int k = src[i];
            d_best[p][ei[k]] = ~0ull;
            d_best[p][ei[EE + k]] = ~0ull;
        }
        if (t == 0) d_lcnt[p] = 0;
        __syncthreads();
        for (int base = 0; base < total; base += 256) {
            int idx = base + t;
            bool want = false;
            int k = 0, u = 0, v = 0;
            unsigned long long key = 0;
            if (idx < total) {
                k = src[idx];
                u = ei[k]; v = ei[EE + k];
                if (!(d_used[u] | d_used[v])) {
                    want = true;
                    key = d_key[k];
                }
            }
            unsigned mask = __ballot_sync(0xFFFFFFFFu, want);
            if (mask) {
                int leader = __ffs(mask) - 1;
                int bpos = 0;
                if (lane == leader) bpos = atomicAdd(&d_lcnt[p], __popc(mask));
                bpos = __shfl_sync(0xFFFFFFFFu, bpos, leader);
                if (want) {
                    dst[bpos + __popc(mask & ((1u << lane) - 1))] = k;
                    atomicMin(&d_best[p][u], key);
                    if (v != u) atomicMin(&d_best[p][v], key);
                }
            }
        }
        __syncthreads();
        int cnt = d_lcnt[p];
        if (cnt == 0) return;
        for (int idx = t; idx < cnt; idx += 256) {
            int k = dst[idx];
            int u = ei[k], v = ei[EE + k];
            unsigned long long key = d_key[k];
            if (key == d_best[p][u] && key == d_best[p][v]) {
                d_used[u] = 1; d_used[v] = 1;
                int rep = min(u, v), oth = max(u, v);
                d_cluster[u] = rep; d_cluster[v] = rep;
                d_nscore[rep] = d_score[k];
                d_addsrc[rep] = oth;
            }
        }
        __syncthreads();
    }
}

__global__ void __launch_bounds__(256) k_match(const int* __restrict__ ei,
                                               const float* __restrict__ pb) {
    const unsigned nb = gridDim.x;
    const int tid = blockIdx.x * blockDim.x + threadIdx.x;
    const int nthr = nb * blockDim.x;
    const int lane = threadIdx.x & 31;
    unsigned gen = 0;

    float pbv = pb[0];
    for (int k = tid; k < EE; k += nthr) {
        int u = ei[k], v = ei[EE + k];
        float e = d_a[u] + d_b[v] + pbv;
        d_e[k] = e;
        atomicMax(&d_m[v], fenc(e));
    }
    gen++; gridbar(nb, &gen);

    for (int k = tid; k < EE; k += nthr) {
        int v = ei[EE + k];
        float ex = expf(d_e[k] - fdec(d_m[v]));
        d_ex[k] = ex;
        atomicAdd(&d_sum[v], ex);
    }
    gen++; gridbar(nb, &gen);

    for (int r = 0; r < ROUNDS; r++) {
        int p = r & 1;
        int total = (r == 0) ? EE : *((volatile int*)&d_lcnt[p ^ 1]);
        if (r > 0 && total <= SB_THRESH) {
            // frontier small: block 0 finishes alone with cheap barriers
            if (blockIdx.x != 0) return;
            sb_tail(ei, r);
            return;
        }
        for (int i = tid; i < NN; i += nthr) d_best[p ^ 1][i] = ~0ull;
        const int* src = d_list[p ^ 1];
        int* dst = d_list[p];
        int iters = (total + nthr - 1) / nthr;
        for (int j = 0; j < iters; j++) {
            int idx = tid + j * nthr;
            bool valid = idx < total;
            int k = 0, u = 0, v = 0;
            unsigned long long key = 0;
            bool want = false;
            if (valid) {
                k = (r == 0) ? idx : ((volatile const int*)src)[idx];
                u = ei[k]; v = ei[EE + k];
                int uu = *((volatile int*)&d_used[u]);
                int vv = *((volatile int*)&d_used[v]);
                if (!(uu | vv)) {
                    want = true;
                    if (r == 0) {
                        float s = d_ex[k] / d_sum[v] + 0.5f;
                        d_score[k] = s;
                        key = ((unsigned long long)(~__float_as_uint(s)) << 32) | (unsigned)k;
                        d_key[k] = key;
                    } else {
                        key = d_key[k];
                    }
                }
            }
            unsigned mask = __ballot_sync(0xFFFFFFFFu, want);
            if (mask) {
                int leader = __ffs(mask) - 1;
                int base = 0;
                if (lane == leader) base = atomicAdd(&d_lcnt[p], __popc(mask));
                base = __shfl_sync(0xFFFFFFFFu, base, leader);
                if (want) {
                    dst[base + __popc(mask & ((1u << lane) - 1))] = k;
                    atomicMin(&d_best[p][u], key);
                    if (v != u) atomicMin(&d_best[p][v], key);
                }
            }
        }
        gen++; gridbar(nb, &gen);
        int cnt = *((volatile int*)&d_lcnt[p]);
        if (cnt == 0) break;
        if (tid == 0) atomicExch(&d_lcnt[p ^ 1], 0);
        for (int idx = tid; idx < cnt; idx += nthr) {
            int k = ((volatile const int*)dst)[idx];
            int u = ei[k], v = ei[EE + k];
            unsigned long long key = d_key[k];
            unsigned long long bu = *((volatile unsigned long long*)&d_best[p][u]);
            unsigned long long bv = *((volatile unsigned long long*)&d_best[p][v]);
            if (key == bu && key == bv) {
                d_used[u] = 1; d_used[v] = 1;
                int rep = min(u, v), oth = max(u, v);
                d_cluster[u] = rep; d_cluster[v] = rep;
                d_nscore[rep] = d_score[k];
                d_addsrc[rep] = oth;
            }
        }
        gen++; gridbar(nb, &gen);
    }
}

// ---------------- valid-node compaction scan (single block) ----------------
__global__ void __launch_bounds__(1024) k_validscan() {
    __shared__ int ssum[1024];
    int t = threadIdx.x;
    int base = t * 32;
    unsigned flags = 0;
    int s = 0;
#pragma unroll
    for (int j = 0; j < 32; j++) {
        int ok = (d_cluster[base + j] == base + j) ? 1 : 0;
        flags |= ((unsigned)ok << j);
        s += ok;
    }
    ssum[t] = s;
    __syncthreads();
    for (int off = 1; off < 1024; off <<= 1) {
        int v = (t >= off) ? ssum[t - off] : 0;
        __syncthreads();
        ssum[t] += v;
        __syncthreads();
    }
    int ex = ssum[t] - s;
#pragma unroll
    for (int j = 0; j < 32; j++) {
        if ((flags >> j) & 1u) {
            d_cmap[base + j] = ex;
            d_nodes[ex] = base + j;
            ex++;
        }
    }
    if (t == 1023) {
        d_nvalid = ex;
        d_nvalid_pad = (ex + 127) & ~127;
    }
}

// pooled node features over COMPACT rows, K-padded, split into bf16 hi/lo
__global__ void k_pxsplit(const float* __restrict__ x) {
    long long idx = (long long)blockIdx.x * blockDim.x + threadIdx.x;
    if (idx >= (long long)NN * KP1) return;
    int i = (int)(idx / KP1), f = (int)(idx % KP1);
    if (i >= d_nvalid_pad) return;
    float val = 0.f;
    if (i < d_nvalid && f < FIN) {
        int n = d_nodes[i];
        val = x[(size_t)n * FIN + f];
        int o = d_addsrc[n];
        if (o >= 0 && o != n) val += x[(size_t)o * FIN + f];
        val *= d_nscore[n];
    }
    bf16split(val, &d_Ah[idx], &d_Al[idx]);
}

// dedup coarsened edges (compact ids); out-degree (norm) + in-degree (CSR)
__global__ void k_dedup(const int* __restrict__ ei) {
    int k = blockIdx.x * blockDim.x + threadIdx.x;
    if (k >= EE) return;
    int cun = d_cluster[ei[k]], cvn = d_cluster[ei[EE + k]];
    if (cun == cvn) return;
    int cu = d_cmap[cun], cv = d_cmap[cvn];
    unsigned key = (unsigned)cu * (unsigned)NN + (unsigned)cv;
    unsigned slot = (key * 2654435761u) >> 14;
    slot &= (TS - 1);
    while (true) {
        unsigned prev = atomicCAS(&d_table[slot], 0xFFFFFFFFu, key);
        if (prev == 0xFFFFFFFFu) {
            int i = atomicAdd(&d_M, 1);
            d_cu[i] = cu; d_cv[i] = cv;
            atomicAdd(&d_deg[cu], 1.0f);
            atomicAdd(&d_indeg[cv], 1);
            return;
        }
        if (prev == key) return;
        slot = (slot + 1) & (TS - 1);
    }
}

// single-block exclusive scan of in-degrees (compact space) + dis from deg
__global__ void __launch_bounds__(1024) k_scan() {
    __shared__ int ssum[1024];
    int t = threadIdx.x;
    int base = t * 32;
    int loc[32];
    int s = 0;
#pragma unroll
    for (int j = 0; j < 32; j++) { loc[j] = d_indeg[base + j]; s += loc[j]; }
    ssum[t] = s;
    __syncthreads();
    for (int off = 1; off < 1024; off <<= 1) {
        int v = (t >= off) ? ssum[t - off] : 0;
        __syncthreads();
        ssum[t] += v;
        __syncthreads();
    }
    int ex = ssum[t] - s;
#pragma unroll
    for (int j = 0; j < 32; j++) {
        d_off[base + j] = ex;
        d_fill[base + j] = ex;
        ex += loc[j];
        float d = d_deg[base + j];
        d_dis[base + j] = (d > 0.f) ? rsqrtf(d) : 0.f;
    }
    if (t == 1023) d_off[NN] = ex;
}

__global__ void k_csrfill() {
    int i = blockIdx.x * blockDim.x + threadIdx.x;
    if (i >= d_M) return;
    int pos = atomicAdd(&d_fill[d_cv[i]], 1);
    d_adj[pos] = d_cu[i];
}

// ---------------- tensor-core split-bf16 GEMM (128x256 tile, 3-stage) -----
__device__ __forceinline__ void ldsm_x4(unsigned& r0, unsigned& r1, unsigned& r2, unsigned& r3,
                                        unsigned addr) {
    asm volatile("ldmatrix.sync.aligned.m8n8.x4.shared.b16 {%0,%1,%2,%3}, [%4];\n"
                 : "=r"(r0), "=r"(r1), "=r"(r2), "=r"(r3) : "r"(addr));
}
__device__ __forceinline__ void ldsm_x2(unsigned& r0, unsigned& r1, unsigned addr) {
    asm volatile("ldmatrix.sync.aligned.m8n8.x2.shared.b16 {%0,%1}, [%2];\n"
                 : "=r"(r0), "=r"(r1) : "r"(addr));
}
__device__ __forceinline__ void mma_bf16(float* c, const unsigned* a, const unsigned* b) {
    asm volatile("mma.sync.aligned.m16n8k16.row.col.f32.bf16.bf16.f32 "
                 "{%0,%1,%2,%3},{%4,%5,%6,%7},{%8,%9},{%0,%1,%2,%3};\n"
                 : "+f"(c[0]), "+f"(c[1]), "+f"(c[2]), "+f"(c[3])
                 : "r"(a[0]), "r"(a[1]), "r"(a[2]), "r"(a[3]), "r"(b[0]), "r"(b[1]));
}
__device__ __forceinline__ void cpasync16(void* dst, const void* src) {
    unsigned d = (unsigned)__cvta_generic_to_shared(dst);
    asm volatile("cp.async.cg.shared.global [%0], [%1], 16;\n" :: "r"(d), "l"(src));
}

#define SKS 40                       // smem row stride (elems): 80B, 16B-aligned
#define TA (128 * SKS)               // A tile elems per array
#define TB (256 * SKS)               // B tile elems per array
#define STAGE_ELEMS (2 * TA + 2 * TB)
#define GSMEM (3 * STAGE_ELEMS * 2)  // 184320 bytes

__device__ __forceinline__ void g_load_stage(
    __nv_bfloat16* st, int t, int bm, int bn, int k0, int K,
    const __nv_bfloat16* Ah, const __nv_bfloat16* Al,
    const __nv_bfloat16* Bh, const __nv_bfloat16* Bl) {
#pragma unroll
    for (int it = 0; it < 2; it++) {
        int i = t + it * 256;
        int rr = i >> 2, cc8 = (i & 3) * 8;
        cpasync16(&st[0 * TA + rr * SKS + cc8], Ah + (size_t)(bm + rr) * K + k0 + cc8);
        cpasync16(&st[1 * TA + rr * SKS + cc8], Al + (size_t)(bm + rr) * K + k0 + cc8);
    }
#pragma unroll
    for (int it = 0; it < 4; it++) {
        int i = t + it * 256;
        int rr = i >> 2, cc8 = (i & 3) * 8;
        cpasync16(&st[2 * TA + rr * SKS + cc8], Bh + (size_t)(bn + rr) * K + k0 + cc8);
        cpasync16(&st[2 * TA + TB + rr * SKS + cc8], Bl + (size_t)(bn + rr) * K + k0 + cc8);
    }
}

__global__ __launch_bounds__(256, 1) void k_mma_gemm(
    const __nv_bfloat16* __restrict__ Ah, const __nv_bfloat16* __restrict__ Al,
    const __nv_bfloat16* __restrict__ Bh, const __nv_bfloat16* __restrict__ Bl,
    float* __restrict__ Cm, int K) {
    extern __shared__ __nv_bfloat16 smem[];
    const int bm = blockIdx.y * 128, bn = blockIdx.x * 256;
    if (bm >= d_nvalid_pad) return;
    const int t = threadIdx.x;
    const int warp = t >> 5, lane = t & 31;
    const int wm = warp & 1, wn = warp >> 1;          // 2 x 4 warp grid
    const int mrow0 = wm * 64, nrow0 = wn * 64;       // 64x64 per warp
    const int m4 = lane >> 3, r8 = lane & 7;
    const int mB = (lane >> 3) & 1;

    float acc[4][8][4];
#pragma unroll
    for (int mi = 0; mi < 4; mi++)
#pragma unroll
        for (int ni = 0; ni < 8; ni++)
#pragma unroll
            for (int r = 0; r < 4; r++) acc[mi][ni][r] = 0.f;

    const int KT = K / 32;
    g_load_stage(smem, t, bm, bn, 0, K, Ah, Al, Bh, Bl);
    asm volatile("cp.async.commit_group;\n" ::: "memory");
    g_load_stage(smem + STAGE_ELEMS, t, bm, bn, 32, K, Ah, Al, Bh, Bl);
    asm volatile("cp.async.commit_group;\n" ::: "memory");

    for (int kt = 0; kt < KT; kt++) {
        if (kt + 2 < KT)
            g_load_stage(smem + ((kt + 2) % 3) * STAGE_ELEMS, t, bm, bn, (kt + 2) * 32, K,
                         Ah, Al, Bh, Bl);
        asm volatile("cp.async.commit_group;\n" ::: "memory");
        asm volatile("cp.async.wait_group 2;\n" ::: "memory");
        __syncthreads();

        __nv_bfloat16* st = smem + (kt % 3) * STAGE_ELEMS;
        __nv_bfloat16* sAh = st;
        __nv_bfloat16* sAl = st + TA;
        __nv_bfloat16* sBh = st + 2 * TA;
        __nv_bfloat16* sBl = st + 2 * TA + TB;

#pragma unroll
        for (int ks = 0; ks < 2; ks++) {
            unsigned ah[4][4], al[4][4], bh[8][2], bl[8][2];
#pragma unroll
            for (int mi = 0; mi < 4; mi++) {
                int rr = mrow0 + mi * 16 + (m4 & 1) * 8 + r8;
                int col = (m4 >> 1) * 8 + ks * 16;
                ldsm_x4(ah[mi][0], ah[mi][1], ah[mi][2], ah[mi][3],
                        (unsigned)__cvta_generic_to_shared(&sAh[rr * SKS + col]));
                ldsm_x4(al[mi][0], al[mi][1], al[mi][2], al[mi][3],
                        (unsigned)__cvta_generic_to_shared(&sAl[rr * SKS + col]));
            }
#pragma unroll
            for (int ni = 0; ni < 8; ni++) {
                int rr = nrow0 + ni * 8 + r8;
                int col = mB * 8 + ks * 16;
                ldsm_x2(bh[ni][0], bh[ni][1],
                        (unsigned)__cvta_generic_to_shared(&sBh[rr * SKS + col]));
                ldsm_x2(bl[ni][0], bl[ni][1],
                        (unsigned)__cvta_generic_to_shared(&sBl[rr * SKS + col]));
            }
#pragma unroll
            for (int mi = 0; mi < 4; mi++)
#pragma unroll
                for (int ni = 0; ni < 8; ni++) {
                    mma_bf16(acc[mi][ni], ah[mi], bh[ni]);
                    mma_bf16(acc[mi][ni], ah[mi], bl[ni]);
                    mma_bf16(acc[mi][ni], al[mi], bh[ni]);
                }
        }
        __syncthreads();
    }
#pragma unroll
    for (int mi = 0; mi < 4; mi++) {
        int r0 = bm + mrow0 + mi * 16 + (lane >> 2);
#pragma unroll
        for (int ni = 0; ni < 8; ni++) {
            int c0 = bn + nrow0 + ni * 8 + (lane & 3) * 2;
            *(float2*)&Cm[(size_t)r0 * ND + c0] = make_float2(acc[mi][ni][0], acc[mi][ni][1]);
            *(float2*)&Cm[(size_t)(r0 + 8) * ND + c0] = make_float2(acc[mi][ni][2], acc[mi][ni][3]);
        }
    }
}

// ---------------- CSR gather + fused epilogue (compact rows) --------------
__device__ __forceinline__ unsigned packbf2(__nv_bfloat16 x, __nv_bfloat16 y) {
    return (unsigned)__bfloat16_as_ushort(x) | ((unsigned)__bfloat16_as_ushort(y) << 16);
}

__global__ void __launch_bounds__(128) k_gather1(const float* __restrict__ Y,
                                                 const float* __restrict__ bias,
                                                 const float* __restrict__ bn) {
    int i = blockIdx.x, t = threadIdx.x;
    if (i >= d_nvalid_pad) return;
    int c = t * 4;
    if (i >= d_nvalid) {
        *(uint2*)(d_H1h + (size_t)i * CC + c) = make_uint2(0u, 0u);
        *(uint2*)(d_H1l + (size_t)i * CC + c) = make_uint2(0u, 0u);
        return;
    }
    float4 y0 = *(const float4*)(Y + (size_t)i * ND + c);
    float a0 = y0.x, a1 = y0.y, a2 = y0.z, a3 = y0.w;
    float disv = d_dis[i];
    int e = d_off[i], end = d_off[i + 1];
    for (; e < end; e++) {
        int cu = d_adj[e];
        float nrm = -disv * d_dis[cu];
        float4 y = *(const float4*)(Y + (size_t)cu * ND + CC + c);
        a0 += nrm * y.x; a1 += nrm * y.y; a2 += nrm * y.z; a3 += nrm * y.w;
    }
    float v[4] = {a0, a1, a2, a3};
    __nv_bfloat16 h[4], l[4];
#pragma unroll
    for (int j = 0; j < 4; j++) {
        float val = v[j] + bias[c + j];
        val = (val - bn[2 * CC + c + j]) * rsqrtf(bn[3 * CC + c + j] + 1e-5f) * bn[c + j]
              + bn[CC + c + j];
        val = fmaxf(val, 0.f);
        bf16split(val, &h[j], &l[j]);
    }
    *(uint2*)(d_H1h + (size_t)i * CC + c) = make_uint2(packbf2(h[0], h[1]), packbf2(h[2], h[3]));
    *(uint2*)(d_H1l + (size_t)i * CC + c) = make_uint2(packbf2(l[0], l[1]), packbf2(l[2], l[3]));
}

__global__ void __launch_bounds__(128) k_gather2(const float* __restrict__ Y,
                                                 const float* __restrict__ bias,
                                                 const float* __restrict__ bn,
                                                 float* __restrict__ H) {
    int i = blockIdx.x, t = threadIdx.x;
    if (i >= d_nvalid) return;
    int c = t * 4;
    float4 y0 = *(const float4*)(Y + (size_t)i * ND + c);
    float a0 = y0.x, a1 = y0.y, a2 = y0.z, a3 = y0.w;
    float disv = d_dis[i];
    int e = d_off[i], end = d_off[i + 1];
    for (; e < end; e++) {
        int cu = d_adj[e];
        float nrm = -disv * d_dis[cu];
        float4 y = *(const float4*)(Y + (size_t)cu * ND + CC + c);
        a0 += nrm * y.x; a1 += nrm * y.y; a2 += nrm * y.z; a3 += nrm * y.w;
    }
    float v[4] = {a0, a1, a2, a3};
    float o[4];
#pragma unroll
    for (int j = 0; j < 4; j++) {
        float val = v[j] + bias[c + j];
        val = (val - bn[2 * CC + c + j]) * rsqrtf(bn[3 * CC + c + j] + 1e-5f) * bn[c + j]
              + bn[CC + c + j];
        o[j] = fmaxf(val, 0.f);
    }
    *(float4*)(H + (size_t)i * CC + c) = make_float4(o[0], o[1], o[2], o[3]);
}

// per-graph max+mean over valid nodes (H in compact rows)
__global__ void k_pool(const float* __restrict__ H, const int* __restrict__ batch) {
    __shared__ int sb[64];
    __shared__ int scm[64];
    __shared__ unsigned char sv[64];
    int base = blockIdx.x * 64;
    int t = threadIdx.x;
    if (t < 64) {
        int n = base + t;
        sb[t] = batch[n];
        bool val = (d_cluster[n] == n);
        sv[t] = val ? 1 : 0;
        scm[t] = val ? d_cmap[n] : 0;
    }
    __syncthreads();
    int c0 = t, c1 = t + 256;
    float mx0 = 0.f, mx1 = 0.f, s0 = 0.f, s1 = 0.f;
    int cnt = 0, curb = -1;
    for (int i = 0; i < 64; i++) {
        int b = sb[i];
        if (b != curb) {
            if (curb >= 0) {
                atomicMax((unsigned*)&d_gmax[curb * CC + c0], __float_as_uint(mx0));
                atomicMax((unsigned*)&d_gmax[curb * CC + c1], __float_as_uint(mx1));
                atomicAdd(&d_gsum[curb * CC + c0], s0);
                atomicAdd(&d_gsum[curb * CC + c1], s1);
                if (t == 0) atomicAdd(&d_cnt[curb], (float)cnt);
            }
            curb = b; mx0 = mx1 = s0 = s1 = 0.f; cnt = 0;
        }
        if (sv[i]) {
            const float* hr = H + (size_t)scm[i] * CC;
            float h0 = hr[c0], h1 = hr[c1];
            mx0 = fmaxf(mx0, h0); mx1 = fmaxf(mx1, h1);
            s0 += h0; s1 += h1; cnt++;
        }
    }
    if (curb >= 0) {
        atomicMax((unsigned*)&d_gmax[curb * CC + c0], __float_as_uint(mx0));
        atomicMax((unsigned*)&d_gmax[curb * CC + c1], __float_as_uint(mx1));
        atomicAdd(&d_gsum[curb * CC + c0], s0);
        atomicAdd(&d_gsum[curb * CC + c1], s1);
        if (t == 0) atomicAdd(&d_cnt[curb], (float)cnt);
    }
}

__global__ void k_readout(const float* __restrict__ l1w, const float* __restrict__ l1b,
                          const float* __restrict__ l2w, const float* __restrict__ l2b,
                          const float* __restrict__ l3w, const float* __restrict__ l3b,
                          const float* __restrict__ bn3, const float* __restrict__ bn4,
                          float* __restrict__ out) {
    int b = blockIdx.x, t = threadIdx.x;
    __shared__ float g[1024], g1[512], g2[256], zz[4];
    float cn = fmaxf(d_cnt[b], 1.f);
    g[t] = d_gmax[b * CC + t];
    g[CC + t] = d_gsum[b * CC + t] / cn;
    __syncthreads();
    {
        float acc = l1b[t];
        for (int k = 0; k < 1024; k++) acc += g[k] * l1w[k * 512 + t];
        acc = (acc - bn3[1024 + t]) * rsqrtf(bn3[1536 + t] + 1e-5f) * bn3[t] + bn3[512 + t];
        g1[t] = fmaxf(acc, 0.f);
    }
    __syncthreads();
    if (t < 256) {
        float acc = l2b[t];
        for (int k = 0; k < 512; k++) acc += g1[k] * l2w[k * 256 + t];
        acc = (acc - bn4[512 + t]) * rsqrtf(bn4[768 + t] + 1e-5f) * bn4[t] + bn4[256 + t];
        acc = fmaxf(acc, 0.f);
        g2[t] = acc;
        out[32 + b * 256 + t] = acc;
    }
    __syncthreads();
    if (t < 4) {
        float acc = l3b[t];
        for (int k = 0; k < 256; k++) acc += g2[k] * l3w[k * 4 + t];
        zz[t] = fmaxf(acc, 0.f);
    }
    __syncthreads();
    if (t < 4) {
        float m = fmaxf(fmaxf(zz[0], zz[1]), fmaxf(zz[2], zz[3]));
        float s = expf(zz[0] - m) + expf(zz[1] - m) + expf(zz[2] - m) + expf(zz[3] - m);
        out[b * 4 + t] = zz[t] - m - logf(s);
    }
}

extern "C" void kernel_launch(void* const* d_in, const int* in_sizes, int n_in,
                              void* d_out, int out_size) {
    const float* x      = (const float*)d_in[0];
    const int*   ei     = (const int*)d_in[1];
    const int*   batch  = (const int*)d_in[2];
    const float* pool_w = (const float*)d_in[3];
    const float* pool_b = (const float*)d_in[4];
    const float* c1w0   = (const float*)d_in[5];
    const float* c1w1   = (const float*)d_in[6];
    const float* c1b    = (const float*)d_in[7];
    const float* c2w0   = (const float*)d_in[8];
    const float* c2w1   = (const float*)d_in[9];
    const float* c2b    = (const float*)d_in[10];
    const float* bn1    = (const float*)d_in[11];
    const float* bn2    = (const float*)d_in[12];
    const float* bn3    = (const float*)d_in[13];
    const float* bn4    = (const float*)d_in[14];
    const float* l1w    = (const float*)d_in[15];
    const float* l1b    = (const float*)d_in[16];
    const float* l2w    = (const float*)d_in[17];
    const float* l2b    = (const float*)d_in[18];
    const float* l3w    = (const float*)d_in[19];
    const float* l3b    = (const float*)d_in[20];
    float* out = (float*)d_out;

    __nv_bfloat16 *p_Ah, *p_Al, *p_W1h, *p_W1l, *p_W2h, *p_W2l, *p_H1h, *p_H1l;
    float *p_Y, *p_H2;
    cudaGetSymbolAddress((void**)&p_Ah, d_Ah);
    cudaGetSymbolAddress((void**)&p_Al, d_Al);
    cudaGetSymbolAddress((void**)&p_W1h, d_W1h);
    cudaGetSymbolAddress((void**)&p_W1l, d_W1l);
    cudaGetSymbolAddress((void**)&p_W2h, d_W2h);
    cudaGetSymbolAddress((void**)&p_W2l, d_W2l);
    cudaGetSymbolAddress((void**)&p_H1h, d_H1h);
    cudaGetSymbolAddress((void**)&p_H1l, d_H1l);
    cudaGetSymbolAddress((void**)&p_Y, d_Y);
    cudaGetSymbolAddress((void**)&p_H2, d_H2);

    static int smem_set = 0;
    if (!smem_set) {
        cudaFuncSetAttribute(k_mma_gemm, cudaFuncAttributeMaxDynamicSharedMemorySize, GSMEM);
        smem_set = 1;
    }

    k_init<<<TS / 256, 256>>>();
    k_packw1<<<(ND * KP1 + 255) / 256, 256>>>(c1w0, c1w1);
    k_packw2<<<(ND * CC + 255) / 256, 256>>>(c2w0, c2w1);
    k_node_dots<<<NN / 8, 256>>>(x, pool_w);

    k_match<<<MBLK, 256>>>(ei, pool_b);
    k_validscan<<<1, 1024>>>();

    k_pxsplit<<<(int)(((long long)NN * KP1 + 255) / 256), 256>>>(x);
    k_dedup<<<EE / 256, 256>>>(ei);
    k_scan<<<1, 1024>>>();
    k_csrfill<<<EE / 256, 256>>>();

    // conv1 (compact rows): [M,1056] x [1056,1024]
    k_mma_gemm<<<dim3(ND / 256, NN / 128), 256, GSMEM>>>(p_Ah, p_Al, p_W1h, p_W1l, p_Y, KP1);
    k_gather1<<<NN, 128>>>(p_Y, c1b, bn1);

    // conv2 (compact rows): [M,512] x [512,1024]
    k_mma_gemm<<<dim3(ND / 256, NN / 128), 256, GSMEM>>>(p_H1h, p_H1l, p_W2h, p_W2l, p_Y, CC);
    k_gather2<<<NN, 128>>>(p_Y, c2b, bn2, p_H2);

    // pooling + readout
    k_pool<<<NN / 64, 256>>>(p_H2, batch);
    k_readout<<<BB, 512>>>(l1w, l1b, l2w, l2b, l3w, l3b, bn3, bn4, out);
}

// round 14
// speedup vs baseline: 1.0710x; 1.0710x over previous
#include <cuda_runtime.h>
#include <cuda_bf16.h>
#include <math.h>

#define NN 32768
#define EE 131072
#define BB 8
#define FIN 1025
#define KP1 1056        // K padded (multiple of 32)
#define CC 512
#define ND 1024
#define TS (1<<18)
#define ROUNDS 96
#define MBLK 148
#define NB2 24          // shrunk matching grid
#define SHRINK_T 16384  // frontier threshold to shrink

// ---------------- device scratch (static, no allocs) ----------------
__device__ float d_a[NN], d_b[NN];
__device__ float d_e[EE], d_ex[EE], d_score[EE];
__device__ unsigned d_m[NN];
__device__ float d_sum[NN];
__device__ unsigned long long d_key[EE];
__device__ int d_used[NN];
__device__ unsigned long long d_best[2][NN];
__device__ int d_list[2][EE];
__device__ int d_lcnt[2];
__device__ unsigned g_arrive;
__device__ unsigned g_arrive2;
__device__ int d_cluster[NN];
__device__ float d_nscore[NN];
__device__ int d_addsrc[NN];
__device__ unsigned d_table[TS];
__device__ int d_M;
__device__ int d_cu[EE], d_cv[EE];       // compact indices
__device__ float d_deg[NN], d_dis[NN];   // compact indexed
__device__ int d_indeg[NN];              // compact indexed
__device__ int d_off[NN + 1];
__device__ int d_fill[NN];
__device__ int d_adj[EE];
__device__ int d_nvalid, d_nvalid_pad;
__device__ int d_cmap[NN];               // node -> compact
__device__ int d_nodes[NN];              // compact -> node

__device__ __nv_bfloat16 d_Ah[(size_t)NN * KP1];
__device__ __nv_bfloat16 d_Al[(size_t)NN * KP1];
__device__ __nv_bfloat16 d_W1h[(size_t)ND * KP1];
__device__ __nv_bfloat16 d_W1l[(size_t)ND * KP1];
__device__ __nv_bfloat16 d_W2h[(size_t)ND * CC];
__device__ __nv_bfloat16 d_W2l[(size_t)ND * CC];
__device__ __nv_bfloat16 d_H1h[(size_t)NN * CC];
__device__ __nv_bfloat16 d_H1l[(size_t)NN * CC];
__device__ float d_Y[(size_t)NN * ND];
__device__ float d_H2[(size_t)NN * CC];
__device__ float d_gmax[BB * CC], d_gsum[BB * CC], d_cnt[BB];

__device__ __forceinline__ unsigned fenc(float f) {
    unsigned u = __float_as_uint(f);
    return (u & 0x80000000u) ? ~u : (u | 0x80000000u);
}
__device__ __forceinline__ float fdec(unsigned u) {
    return (u & 0x80000000u) ? __uint_as_float(u ^ 0x80000000u)
                             : __uint_as_float(~u);
}
__device__ __forceinline__ void bf16split(float v, __nv_bfloat16* hi, __nv_bfloat16* lo) {
    __nv_bfloat16 h = __float2bfloat16(v);
    *hi = h;
    *lo = __float2bfloat16(v - __bfloat162float(h));
}

// ---------------- init ----------------
__global__ void k_init() {
    int i = blockIdx.x * blockDim.x + threadIdx.x;
    if (i < TS) d_table[i] = 0xFFFFFFFFu;
    if (i < NN) {
        d_m[i] = 0u; d_sum[i] = 0.f; d_used[i] = 0;
        d_cluster[i] = i; d_nscore[i] = 1.f; d_addsrc[i] = -1;
        d_deg[i] = 0.f; d_indeg[i] = 0;
        d_best[0][i] = ~0ull; d_best[1][i] = ~0ull;
    }
    if (i < BB * CC) { d_gmax[i] = 0.f; d_gsum[i] = 0.f; }
    if (i < BB) d_cnt[i] = 0.f;
    if (i == 0) { d_M = 0; g_arrive = 0u; g_arrive2 = 0u; d_lcnt[0] = 0; d_lcnt[1] = 0; }
}

// pack weights TRANSPOSED [n][k] + split hi/lo
__global__ void k_packw1(const float* __restrict__ w0, const float* __restrict__ w1) {
    int idx = blockIdx.x * blockDim.x + threadIdx.x;
    if (idx >= ND * KP1) return;
    int n = idx / KP1, k = idx % KP1;
    float v = 0.f;
    if (k < FIN) v = (n < CC) ? w0[k * CC + n] : w1[k * CC + (n - CC)];
    bf16split(v, &d_W1h[idx], &d_W1l[idx]);
}
__global__ void k_packw2(const float* __restrict__ w0, const float* __restrict__ w1) {
    int idx = blockIdx.x * blockDim.x + threadIdx.x;
    if (idx >= ND * CC) return;
    int n = idx / CC, k = idx % CC;
    float v = (n < CC) ? w0[k * CC + n] : w1[k * CC + (n - CC)];
    bf16split(v, &d_W2h[idx], &d_W2l[idx]);
}

__global__ void k_node_dots(const float* __restrict__ x, const float* __restrict__ pw) {
    int n = blockIdx.x * (blockDim.x / 32) + (threadIdx.x >> 5);
    if (n >= NN) return;
    int lane = threadIdx.x & 31;
    const float* xr = x + (size_t)n * FIN;
    float sa = 0.f, sb = 0.f;
    for (int f = lane; f < FIN; f += 32) {
        float xv = xr[f];
        sa += xv * pw[f];
        sb += xv * pw[FIN + f];
    }
    for (int o = 16; o; o >>= 1) {
        sa += __shfl_down_sync(0xFFFFFFFFu, sa, o);
        sb += __shfl_down_sync(0xFFFFFFFFu, sb, o);
    }
    if (!lane) { d_a[n] = sa; d_b[n] = sb; }
}

// ---------------- persistent matching (softmax + frontier rounds) --------
__device__ __forceinline__ void gridbarX(unsigned* ctr, unsigned nb, unsigned* gen) {
    __syncthreads();
    if (threadIdx.x == 0) {
        __threadfence();
        atomicAdd(ctr, 1u);
        unsigned target = (*gen) * nb;
        while (*((volatile unsigned*)ctr) < target) __nanosleep(32);
    }
    __syncthreads();
}

__global__ void __launch_bounds__(256) k_match(const int* __restrict__ ei,
                                               const float* __restrict__ pb) {
    const unsigned nb = gridDim.x;
    const int tid = blockIdx.x * blockDim.x + threadIdx.x;
    const int lane = threadIdx.x & 31;
    int nthr = nb * blockDim.x;
    unsigned gen = 0, gen2 = 0;
    bool shrunk = false;

    float pbv = pb[0];
    for (int k = tid; k < EE; k += nthr) {
        int u = ei[k], v = ei[EE + k];
        float e = d_a[u] + d_b[v] + pbv;
        d_e[k] = e;
        atomicMax(&d_m[v], fenc(e));
    }
    gen++; gridbarX(&g_arrive, nb, &gen);

    for (int k = tid; k < EE; k += nthr) {
        int v = ei[EE + k];
        float ex = expf(d_e[k] - fdec(d_m[v]));
        d_ex[k] = ex;
        atomicAdd(&d_sum[v], ex);
    }
    gen++; gridbarX(&g_arrive, nb, &gen);

    for (int r = 0; r < ROUNDS; r++) {
        int p = r & 1;
        int total = (r == 0) ? EE : *((volatile int*)&d_lcnt[p ^ 1]);
        if (!shrunk && r > 0 && total <= SHRINK_T) {
            if (blockIdx.x >= NB2) return;   // uniform round boundary, state consistent
            shrunk = true;
            nthr = NB2 * 256;
        }
        for (int i = tid; i < NN; i += nthr) d_best[p ^ 1][i] = ~0ull;
        const int* src = d_list[p ^ 1];
        int* dst = d_list[p];
        int iters = (total + nthr - 1) / nthr;
        for (int j = 0; j < iters; j++) {
            int idx = tid + j * nthr;
            bool valid = idx < total;
            int k = 0, u = 0, v = 0;
            unsigned long long key = 0;
            bool want = false;
            if (valid) {
                k = (r == 0) ? idx : ((volatile const int*)src)[idx];
                u = ei[k]; v = ei[EE + k];
                int uu = *((volatile int*)&d_used[u]);
                int vv = *((volatile int*)&d_used[v]);
                if (!(uu | vv)) {
                    want = true;
                    if (r == 0) {
                        float s = d_ex[k] / d_sum[v] + 0.5f;
                        d_score[k] = s;
                        key = ((unsigned long long)(~__float_as_uint(s)) << 32) | (unsigned)k;
                        d_key[k] = key;
                    } else {
                        key = d_key[k];
                    }
                }
            }
            unsigned mask = __ballot_sync(0xFFFFFFFFu, want);
            if (mask) {
                int leader = __ffs(mask) - 1;
                int base = 0;
                if (lane == leader) base = atomicAdd(&d_lcnt[p], __popc(mask));
                base = __shfl_sync(0xFFFFFFFFu, base, leader);
                if (want) {
                    dst[base + __popc(mask & ((1u << lane) - 1))] = k;
                    atomicMin(&d_best[p][u], key);
                    if (v != u) atomicMin(&d_best[p][v], key);
                }
            }
        }
        if (shrunk) { gen2++; gridbarX(&g_arrive2, NB2, &gen2); }
        else        { gen++;  gridbarX(&g_arrive,  nb,  &gen);  }
        int cnt = *((volatile int*)&d_lcnt[p]);
        if (cnt == 0) break;
        if (tid == 0) atomicExch(&d_lcnt[p ^ 1], 0);
        for (int idx = tid; idx < cnt; idx += nthr) {
            int k = ((volatile const int*)dst)[idx];
            int u = ei[k], v = ei[EE + k];
            unsigned long long key = d_key[k];
            unsigned long long bu = *((volatile unsigned long long*)&d_best[p][u]);
            unsigned long long bv = *((volatile unsigned long long*)&d_best[p][v]);
            if (key == bu && key == bv) {
                d_used[u] = 1; d_used[v] = 1;
                int rep = min(u, v), oth = max(u, v);
                d_cluster[u] = rep; d_cluster[v] = rep;
                d_nscore[rep] = d_score[k];
                d_addsrc[rep] = oth;
            }
        }
        if (shrunk) { gen2++; gridbarX(&g_arrive2, NB2, &gen2); }
        else        { gen++;  gridbarX(&g_arrive,  nb,  &gen);  }
    }
}

// ---------------- valid-node compaction scan (single block) ----------------
__global__ void __launch_bounds__(1024) k_validscan() {
    __shared__ int ssum[1024];
    int t = threadIdx.x;
    int base = t * 32;
    unsigned flags = 0;
    int s = 0;
#pragma unroll
    for (int j = 0; j < 32; j++) {
        int ok = (d_cluster[base + j] == base + j) ? 1 : 0;
        flags |= ((unsigned)ok << j);
        s += ok;
    }
    ssum[t] = s;
    __syncthreads();
    for (int off = 1; off < 1024; off <<= 1) {
        int v = (t >= off) ? ssum[t - off] : 0;
        __syncthreads();
        ssum[t] += v;
        __syncthreads();
    }
    int ex = ssum[t] - s;
#pragma unroll
    for (int j = 0; j < 32; j++) {
        if ((flags >> j) & 1u) {
            d_cmap[base + j] = ex;
            d_nodes[ex] = base + j;
            ex++;
        }
    }
    if (t == 1023) {
        d_nvalid = ex;
        d_nvalid_pad = (ex + 127) & ~127;
    }
}

// pooled node features over COMPACT rows, K-padded, split into bf16 hi/lo
__global__ void k_pxsplit(const float* __restrict__ x) {
    long long idx = (long long)blockIdx.x * blockDim.x + threadIdx.x;
    if (idx >= (long long)NN * KP1) return;
    int i = (int)(idx / KP1), f = (int)(idx % KP1);
    if (i >= d_nvalid_pad) return;
    float val = 0.f;
    if (i < d_nvalid && f < FIN) {
        int n = d_nodes[i];
        val = x[(size_t)n * FIN + f];
        int o = d_addsrc[n];
        if (o >= 0 && o != n) val += x[(size_t)o * FIN + f];
        val *= d_nscore[n];
    }
    bf16split(val, &d_Ah[idx], &d_Al[idx]);
}

// dedup coarsened edges (compact ids); out-degree (norm) + in-degree (CSR)
__global__ void k_dedup(const int* __restrict__ ei) {
    int k = blockIdx.x * blockDim.x + threadIdx.x;
    if (k >= EE) return;
    int cun = d_cluster[ei[k]], cvn = d_cluster[ei[EE + k]];
    if (cun == cvn) return;
    int cu = d_cmap[cun], cv = d_cmap[cvn];
    unsigned key = (unsigned)cu * (unsigned)NN + (unsigned)cv;
    unsigned slot = (key * 2654435761u) >> 14;
    slot &= (TS - 1);
    while (true) {
        unsigned prev = atomicCAS(&d_table[slot], 0xFFFFFFFFu, key);
        if (prev == 0xFFFFFFFFu) {
            int i = atomicAdd(&d_M, 1);
            d_cu[i] = cu; d_cv[i] = cv;
            atomicAdd(&d_deg[cu], 1.0f);
            atomicAdd(&d_indeg[cv], 1);
            return;
        }
        if (prev == key) return;
        slot = (slot + 1) & (TS - 1);
    }
}
__global__ void k_dis() {
    int n = blockIdx.x * blockDim.x + threadIdx.x;
    if (n >= NN) return;
    float d = d_deg[n];
    d_dis[n] = (d > 0.f) ? rsqrtf(d) : 0.f;
}

// single-block exclusive scan of in-degrees (compact space)
__global__ void __launch_bounds__(1024) k_scan() {
    __shared__ int ssum[1024];
    int t = threadIdx.x;
    int base = t * 32;
    int loc[32];
    int s = 0;
#pragma unroll
    for (int j = 0; j < 32; j++) { loc[j] = d_indeg[base + j]; s += loc[j]; }
    ssum[t] = s;
    __syncthreads();
    for (int off = 1; off < 1024; off <<= 1) {
        int v = (t >= off) ? ssum[t - off] : 0;
        __syncthreads();
        ssum[t] += v;
        __syncthreads();
    }
    int ex = ssum[t] - s;
#pragma unroll
    for (int j = 0; j < 32; j++) {
        d_off[base + j] = ex;
        d_fill[base + j] = ex;
        ex += loc[j];
    }
    if (t == 1023) d_off[NN] = ex;
}

__global__ void k_csrfill() {
    int i = blockIdx.x * blockDim.x + threadIdx.x;
    if (i >= d_M) return;
    int pos = atomicAdd(&d_fill[d_cv[i]], 1);
    d_adj[pos] = d_cu[i];
}

// ---------------- tensor-core split-bf16 GEMM (128x256 tile, 3-stage) -----
__device__ __forceinline__ void ldsm_x4(unsigned& r0, unsigned& r1, unsigned& r2, unsigned& r3,
                                        unsigned addr) {
    asm volatile("ldmatrix.sync.aligned.m8n8.x4.shared.b16 {%0,%1,%2,%3}, [%4];\n"
                 : "=r"(r0), "=r"(r1), "=r"(r2), "=r"(r3) : "r"(addr));
}
__device__ __forceinline__ void ldsm_x2(unsigned& r0, unsigned& r1, unsigned addr) {
    asm volatile("ldmatrix.sync.aligned.m8n8.x2.shared.b16 {%0,%1}, [%2];\n"
                 : "=r"(r0), "=r"(r1) : "r"(addr));
}
__device__ __forceinline__ void mma_bf16(float* c, const unsigned* a, const unsigned* b) {
    asm volatile("mma.sync.aligned.m16n8k16.row.col.f32.bf16.bf16.f32 "
                 "{%0,%1,%2,%3},{%4,%5,%6,%7},{%8,%9},{%0,%1,%2,%3};\n"
                 : "+f"(c[0]), "+f"(c[1]), "+f"(c[2]), "+f"(c[3])
                 : "r"(a[0]), "r"(a[1]), "r"(a[2]), "r"(a[3]), "r"(b[0]), "r"(b[1]));
}
__device__ __forceinline__ void cpasync16(void* dst, const void* src) {
    unsigned d = (unsigned)__cvta_generic_to_shared(dst);
    asm volatile("cp.async.cg.shared.global [%0], [%1], 16;\n" :: "r"(d), "l"(src));
}

#define SKS 40                       // smem row stride (elems): 80B, 16B-aligned
#define TA (128 * SKS)               // A tile elems per array
#define TB (256 * SKS)               // B tile elems per array
#define STAGE_ELEMS (2 * TA + 2 * TB)
#define GSMEM (3 * STAGE_ELEMS * 2)  // 184320 bytes

__device__ __forceinline__ void g_load_stage(
    __nv_bfloat16* st, int t, int bm, int bn, int k0, int K,
    const __nv_bfloat16* Ah, const __nv_bfloat16* Al,
    const __nv_bfloat16* Bh, const __nv_bfloat16* Bl) {
#pragma unroll
    for (int it = 0; it < 2; it++) {
        int i = t + it * 256;
        int rr = i >> 2, cc8 = (i & 3) * 8;
        cpasync16(&st[0 * TA + rr * SKS + cc8], Ah + (size_t)(bm + rr) * K + k0 + cc8);
        cpasync16(&st[1 * TA + rr * SKS + cc8], Al + (size_t)(bm + rr) * K + k0 + cc8);
    }
#pragma unroll
    for (int it = 0; it < 4; it++) {
        int i = t + it * 256;
        int rr = i >> 2, cc8 = (i & 3) * 8;
        cpasync16(&st[2 * TA + rr * SKS + cc8], Bh + (size_t)(bn + rr) * K + k0 + cc8);
        cpasync16(&st[2 * TA + TB + rr * SKS + cc8], Bl + (size_t)(bn + rr) * K + k0 + cc8);
    }
}

__global__ __launch_bounds__(256, 1) void k_mma_gemm(
    const __nv_bfloat16* __restrict__ Ah, const __nv_bfloat16* __restrict__ Al,
    const __nv_bfloat16* __restrict__ Bh, const __nv_bfloat16* __restrict__ Bl,
    float* __restrict__ Cm, int K) {
    extern __shared__ __nv_bfloat16 smem[];
    const int bm = blockIdx.y * 128, bn = blockIdx.x * 256;
    if (bm >= d_nvalid_pad) return;
    const int t = threadIdx.x;
    const int warp = t >> 5, lane = t & 31;
    const int wm = warp & 1, wn = warp >> 1;          // 2 x 4 warp grid
    const int mrow0 = wm * 64, nrow0 = wn * 64;       // 64x64 per warp
    const int m4 = lane >> 3, r8 = lane & 7;
    const int mB = (lane >> 3) & 1;

    float acc[4][8][4];
#pragma unroll
    for (int mi = 0; mi < 4; mi++)
#pragma unroll
        for (int ni = 0; ni < 8; ni++)
#pragma unroll
            for (int r = 0; r < 4; r++) acc[mi][ni][r] = 0.f;

    const int KT = K / 32;
    g_load_stage(smem, t, bm, bn, 0, K, Ah, Al, Bh, Bl);
    asm volatile("cp.async.commit_group;\n" ::: "memory");
    g_load_stage(smem + STAGE_ELEMS, t, bm, bn, 32, K, Ah, Al, Bh, Bl);
    asm volatile("cp.async.commit_group;\n" ::: "memory");

    for (int kt = 0; kt < KT; kt++) {
        if (kt + 2 < KT)
            g_load_stage(smem + ((kt + 2) % 3) * STAGE_ELEMS, t, bm, bn, (kt + 2) * 32, K,
                         Ah, Al, Bh, Bl);
        asm volatile("cp.async.commit_group;\n" ::: "memory");
        asm volatile("cp.async.wait_group 2;\n" ::: "memory");
        __syncthreads();

        __nv_bfloat16* st = smem + (kt % 3) * STAGE_ELEMS;
        __nv_bfloat16* sAh = st;
        __nv_bfloat16* sAl = st + TA;
        __nv_bfloat16* sBh = st + 2 * TA;
        __nv_bfloat16* sBl = st + 2 * TA + TB;

#pragma unroll
        for (int ks = 0; ks < 2; ks++) {
            unsigned ah[4][4], al[4][4], bh[8][2], bl[8][2];
#pragma unroll
            for (int mi = 0; mi < 4; mi++) {
                int rr = mrow0 + mi * 16 + (m4 & 1) * 8 + r8;
                int col = (m4 >> 1) * 8 + ks * 16;
                ldsm_x4(ah[mi][0], ah[mi][1], ah[mi][2], ah[mi][3],
                        (unsigned)__cvta_generic_to_shared(&sAh[rr * SKS + col]));
                ldsm_x4(al[mi][0], al[mi][1], al[mi][2], al[mi][3],
                        (unsigned)__cvta_generic_to_shared(&sAl[rr * SKS + col]));
            }
#pragma unroll
            for (int ni = 0; ni < 8; ni++) {
                int rr = nrow0 + ni * 8 + r8;
                int col = mB * 8 + ks * 16;
                ldsm_x2(bh[ni][0], bh[ni][1],
                        (unsigned)__cvta_generic_to_shared(&sBh[rr * SKS + col]));
                ldsm_x2(bl[ni][0], bl[ni][1],
                        (unsigned)__cvta_generic_to_shared(&sBl[rr * SKS + col]));
            }
#pragma unroll
            for (int mi = 0; mi < 4; mi++)
#pragma unroll
                for (int ni = 0; ni < 8; ni++) {
                    mma_bf16(acc[mi][ni], ah[mi], bh[ni]);
                    mma_bf16(acc[mi][ni], ah[mi], bl[ni]);
                    mma_bf16(acc[mi][ni], al[mi], bh[ni]);
                }
        }
        __syncthreads();
    }
#pragma unroll
    for (int mi = 0; mi < 4; mi++) {
        int r0 = bm + mrow0 + mi * 16 + (lane >> 2);
#pragma unroll
        for (int ni = 0; ni < 8; ni++) {
            int c0 = bn + nrow0 + ni * 8 + (lane & 3) * 2;
            *(float2*)&Cm[(size_t)r0 * ND + c0] = make_float2(acc[mi][ni][0], acc[mi][ni][1]);
            *(float2*)&Cm[(size_t)(r0 + 8) * ND + c0] = make_float2(acc[mi][ni][2], acc[mi][ni][3]);
        }
    }
}

// ---------------- CSR gather + fused epilogue (compact rows) --------------
__device__ __forceinline__ unsigned packbf2(__nv_bfloat16 x, __nv_bfloat16 y) {
    return (unsigned)__bfloat16_as_ushort(x) | ((unsigned)__bfloat16_as_ushort(y) << 16);
}

__global__ void __launch_bounds__(128) k_gather1(const float* __restrict__ Y,
                                                 const float* __restrict__ bias,
                                                 const float* __restrict__ bn) {
    int i = blockIdx.x, t = threadIdx.x;
    if (i >= d_nvalid_pad) return;
    int c = t * 4;
    if (i >= d_nvalid) {
        *(uint2*)(d_H1h + (size_t)i * CC + c) = make_uint2(0u, 0u);
        *(uint2*)(d_H1l + (size_t)i * CC + c) = make_uint2(0u, 0u);
        return;
    }
    float4 y0 = *(const float4*)(Y + (size_t)i * ND + c);
    float a0 = y0.x, a1 = y0.y, a2 = y0.z, a3 = y0.w;
    float disv = d_dis[i];
    int e = d_off[i], end = d_off[i + 1];
    for (; e < end; e++) {
        int cu = d_adj[e];
        float nrm = -disv * d_dis[cu];
        float4 y = *(const float4*)(Y + (size_t)cu * ND + CC + c);
        a0 += nrm * y.x; a1 += nrm * y.y; a2 += nrm * y.z; a3 += nrm * y.w;
    }
    float v[4] = {a0, a1, a2, a3};
    __nv_bfloat16 h[4], l[4];
#pragma unroll
    for (int j = 0; j < 4; j++) {
        float val = v[j] + bias[c + j];
        val = (val - bn[2 * CC + c + j]) * rsqrtf(bn[3 * CC + c + j] + 1e-5f) * bn[c + j]
              + bn[CC + c + j];
        val = fmaxf(val, 0.f);
        bf16split(val, &h[j], &l[j]);
    }
    *(uint2*)(d_H1h + (size_t)i * CC + c) = make_uint2(packbf2(h[0], h[1]), packbf2(h[2], h[3]));
    *(uint2*)(d_H1l + (size_t)i * CC + c) = make_uint2(packbf2(l[0], l[1]), packbf2(l[2], l[3]));
}

__global__ void __launch_bounds__(128) k_gather2(const float* __restrict__ Y,
                                                 const float* __restrict__ bias,
                                                 const float* __restrict__ bn,
                                                 float* __restrict__ H) {
    int i = blockIdx.x, t = threadIdx.x;
    if (i >= d_nvalid) return;
    int c = t * 4;
    float4 y0 = *(const float4*)(Y + (size_t)i * ND + c);
    float a0 = y0.x, a1 = y0.y, a2 = y0.z, a3 = y0.w;
    float disv = d_dis[i];
    int e = d_off[i], end = d_off[i + 1];
    for (; e < end; e++) {
        int cu = d_adj[e];
        float nrm = -disv * d_dis[cu];
        float4 y = *(const float4*)(Y + (size_t)cu * ND + CC + c);
        a0 += nrm * y.x; a1 += nrm * y.y; a2 += nrm * y.z; a3 += nrm * y.w;
    }
    float v[4] = {a0, a1, a2, a3};
    float o[4];
#pragma unroll
    for (int j = 0; j < 4; j++) {
        float val = v[j] + bias[c + j];
        val = (val - bn[2 * CC + c + j]) * rsqrtf(bn[3 * CC + c + j] + 1e-5f) * bn[c + j]
              + bn[CC + c + j];
        o[j] = fmaxf(val, 0.f);
    }
    *(float4*)(H + (size_t)i * CC + c) = make_float4(o[0], o[1], o[2], o[3]);
}

// per-graph max+mean over valid nodes (H in compact rows)
__global__ void k_pool(const float* __restrict__ H, const int* __restrict__ batch) {
    __shared__ int sb[64];
    __shared__ int scm[64];
    __shared__ unsigned char sv[64];
    int base = blockIdx.x * 64;
    int t = threadIdx.x;
    if (t < 64) {
        int n = base + t;
        sb[t] = batch[n];
        bool val = (d_cluster[n] == n);
        sv[t] = val ? 1 : 0;
        scm[t] = val ? d_cmap[n] : 0;
    }
    __syncthreads();
    int c0 = t, c1 = t + 256;
    float mx0 = 0.f, mx1 = 0.f, s0 = 0.f, s1 = 0.f;
    int cnt = 0, curb = -1;
    for (int i = 0; i < 64; i++) {
        int b = sb[i];
        if (b != curb) {
            if (curb >= 0) {
                atomicMax((unsigned*)&d_gmax[curb * CC + c0], __float_as_uint(mx0));
                atomicMax((unsigned*)&d_gmax[curb * CC + c1], __float_as_uint(mx1));
                atomicAdd(&d_gsum[curb * CC + c0], s0);
                atomicAdd(&d_gsum[curb * CC + c1], s1);
                if (t == 0) atomicAdd(&d_cnt[curb], (float)cnt);
            }
            curb = b; mx0 = mx1 = s0 = s1 = 0.f; cnt = 0;
        }
        if (sv[i]) {
            const float* hr = H + (size_t)scm[i] * CC;
            float h0 = hr[c0], h1 = hr[c1];
            mx0 = fmaxf(mx0, h0); mx1 = fmaxf(mx1, h1);
            s0 += h0; s1 += h1; cnt++;
        }
    }
    if (curb >= 0) {
        atomicMax((unsigned*)&d_gmax[curb * CC + c0], __float_as_uint(mx0));
        atomicMax((unsigned*)&d_gmax[curb * CC + c1], __float_as_uint(mx1));
        atomicAdd(&d_gsum[curb * CC + c0], s0);
        atomicAdd(&d_gsum[curb * CC + c1], s1);
        if (t == 0) atomicAdd(&d_cnt[curb], (float)cnt);
    }
}

__global__ void k_readout(const float* __restrict__ l1w, const float* __restrict__ l1b,
                          const float* __restrict__ l2w, const float* __restrict__ l2b,
                          const float* __restrict__ l3w, const float* __restrict__ l3b,
                          const float* __restrict__ bn3, const float* __restrict__ bn4,
                          float* __restrict__ out) {
    int b = blockIdx.x, t = threadIdx.x;
    __shared__ float g[1024], g1[512], g2[256], zz[4];
    float cn = fmaxf(d_cnt[b], 1.f);
    g[t] = d_gmax[b * CC + t];
    g[CC + t] = d_gsum[b * CC + t] / cn;
    __syncthreads();
    {
        float acc = l1b[t];
        for (int k = 0; k < 1024; k++) acc += g[k] * l1w[k * 512 + t];
        acc = (acc - bn3[1024 + t]) * rsqrtf(bn3[1536 + t] + 1e-5f) * bn3[t] + bn3[512 + t];
        g1[t] = fmaxf(acc, 0.f);
    }
    __syncthreads();
    if (t < 256) {
        float acc = l2b[t];
        for (int k = 0; k < 512; k++) acc += g1[k] * l2w[k * 256 + t];
        acc = (acc - bn4[512 + t]) * rsqrtf(bn4[768 + t] + 1e-5f) * bn4[t] + bn4[256 + t];
        acc = fmaxf(acc, 0.f);
        g2[t] = acc;
        out[32 + b * 256 + t] = acc;
    }
    __syncthreads();
    if (t < 4) {
        float acc = l3b[t];
        for (int k = 0; k < 256; k++) acc += g2[k] * l3w[k * 4 + t];
        zz[t] = fmaxf(acc, 0.f);
    }
    __syncthreads();
    if (t < 4) {
        float m = fmaxf(fmaxf(zz[0], zz[1]), fmaxf(zz[2], zz[3]));
        float s = expf(zz[0] - m) + expf(zz[1] - m) + expf(zz[2] - m) + expf(zz[3] - m);
        out[b * 4 + t] = zz[t] - m - logf(s);
    }
}

extern "C" void kernel_launch(void* const* d_in, const int* in_sizes, int n_in,
                              void* d_out, int out_size) {
    const float* x      = (const float*)d_in[0];
    const int*   ei     = (const int*)d_in[1];
    const int*   batch  = (const int*)d_in[2];
    const float* pool_w = (const float*)d_in[3];
    const float* pool_b = (const float*)d_in[4];
    const float* c1w0   = (const float*)d_in[5];
    const float* c1w1   = (const float*)d_in[6];
    const float* c1b    = (const float*)d_in[7];
    const float* c2w0   = (const float*)d_in[8];
    const float* c2w1   = (const float*)d_in[9];
    const float* c2b    = (const float*)d_in[10];
    const float* bn1    = (const float*)d_in[11];
    const float* bn2    = (const float*)d_in[12];
    const float* bn3    = (const float*)d_in[13];
    const float* bn4    = (const float*)d_in[14];
    const float* l1w    = (const float*)d_in[15];
    const float* l1b    = (const float*)d_in[16];
    const float* l2w    = (const float*)d_in[17];
    const float* l2b    = (const float*)d_in[18];
    const float* l3w    = (const float*)d_in[19];
    const float* l3b    = (const float*)d_in[20];
    float* out = (float*)d_out;

    __nv_bfloat16 *p_Ah, *p_Al, *p_W1h, *p_W1l, *p_W2h, *p_W2l, *p_H1h, *p_H1l;
    float *p_Y, *p_H2;
    cudaGetSymbolAddress((void**)&p_Ah, d_Ah);
    cudaGetSymbolAddress((void**)&p_Al, d_Al);
    cudaGetSymbolAddress((void**)&p_W1h, d_W1h);
    cudaGetSymbolAddress((void**)&p_W1l, d_W1l);
    cudaGetSymbolAddress((void**)&p_W2h, d_W2h);
    cudaGetSymbolAddress((void**)&p_W2l, d_W2l);
    cudaGetSymbolAddress((void**)&p_H1h, d_H1h);
    cudaGetSymbolAddress((void**)&p_H1l, d_H1l);
    cudaGetSymbolAddress((void**)&p_Y, d_Y);
    cudaGetSymbolAddress((void**)&p_H2, d_H2);

    static int smem_set = 0;
    if (!smem_set) {
        cudaFuncSetAttribute(k_mma_gemm, cudaFuncAttributeMaxDynamicSharedMemorySize, GSMEM);
        smem_set = 1;
    }

    k_init<<<TS / 256, 256>>>();
    k_packw1<<<(ND * KP1 + 255) / 256, 256>>>(c1w0, c1w1);
    k_packw2<<<(ND * CC + 255) / 256, 256>>>(c2w0, c2w1);
    k_node_dots<<<NN / 8, 256>>>(x, pool_w);

    k_match<<<MBLK, 256>>>(ei, pool_b);
    k_validscan<<<1, 1024>>>();

    k_pxsplit<<<(int)(((long long)NN * KP1 + 255) / 256), 256>>>(x);
    k_dedup<<<EE / 256, 256>>>(ei);
    k_dis<<<NN / 256, 256>>>();
    k_scan<<<1, 1024>>>();
    k_csrfill<<<EE / 256, 256>>>();

    // conv1 (compact rows): [M,1056] x [1056,1024]
    k_mma_gemm<<<dim3(ND / 256, NN / 128), 256, GSMEM>>>(p_Ah, p_Al, p_W1h, p_W1l, p_Y, KP1);
    k_gather1<<<NN, 128>>>(p_Y, c1b, bn1);

    // conv2 (compact rows): [M,512] x [512,1024]
    k_mma_gemm<<<dim3(ND / 256, NN / 128), 256, GSMEM>>>(p_H1h, p_H1l, p_W2h, p_W2l, p_Y, CC);
    k_gather2<<<NN, 128>>>(p_Y, c2b, bn2, p_H2);

    // pooling + readout
    k_pool<<<NN / 64, 256>>>(p_H2, batch);
    k_readout<<<BB, 512>>>(l1w, l1b, l2w, l2b, l3w, l3b, bn3, bn4, out);
}

// round 16
// speedup vs baseline: 1.1211x; 1.0468x over previous
#include <cuda_runtime.h>
#include <cuda_bf16.h>
#include <math.h>

#define NN 32768
#define EE 131072
#define BB 8
#define FIN 1025
#define KP1 1056        // K padded (multiple of 32)
#define CC 512
#define ND 1024
#define TS (1<<18)
#define ROUNDS 96
#define MBLK 148

// ---------------- device scratch (static, no allocs) ----------------
__device__ float d_a[NN], d_b[NN];
__device__ float d_e[EE], d_ex[EE], d_score[EE];
__device__ unsigned d_m[NN];
__device__ float d_sum[NN];
__device__ unsigned long long d_key[EE];
__device__ int d_used[NN];
__device__ unsigned long long d_best[2][NN];
__device__ int d_list[2][EE];
__device__ int d_lcnt[2];
__device__ unsigned g_arrive;
__device__ int d_cluster[NN];
__device__ float d_nscore[NN];
__device__ int d_addsrc[NN];
__device__ unsigned d_table[TS];
__device__ int d_M;
__device__ int d_cu[EE], d_cv[EE];       // compact indices
__device__ float d_deg[NN], d_dis[NN];   // compact indexed
__device__ int d_indeg[NN];              // compact indexed
__device__ int d_off[NN + 1];
__device__ int d_fill[NN];
__device__ int d_adj[EE];
__device__ int d_nvalid, d_nvalid_pad;
__device__ int d_cmap[NN];               // node -> compact
__device__ int d_nodes[NN];              // compact -> node

__device__ __nv_bfloat16 d_Ah[(size_t)NN * KP1];
__device__ __nv_bfloat16 d_Al[(size_t)NN * KP1];
__device__ __nv_bfloat16 d_W1h[(size_t)ND * KP1];
__device__ __nv_bfloat16 d_W1l[(size_t)ND * KP1];
__device__ __nv_bfloat16 d_W2h[(size_t)ND * CC];
__device__ __nv_bfloat16 d_W2l[(size_t)ND * CC];
__device__ __nv_bfloat16 d_H1h[(size_t)NN * CC];
__device__ __nv_bfloat16 d_H1l[(size_t)NN * CC];
__device__ float d_Y[(size_t)NN * ND];
__device__ float d_H2[(size_t)NN * CC];
__device__ float d_gmax[BB * CC], d_gsum[BB * CC], d_cnt[BB];

__device__ __forceinline__ unsigned fenc(float f) {
    unsigned u = __float_as_uint(f);
    return (u & 0x80000000u) ? ~u : (u | 0x80000000u);
}
__device__ __forceinline__ float fdec(unsigned u) {
    return (u & 0x80000000u) ? __uint_as_float(u ^ 0x80000000u)
                             : __uint_as_float(~u);
}
__device__ __forceinline__ void bf16split(float v, __nv_bfloat16* hi, __nv_bfloat16* lo) {
    __nv_bfloat16 h = __float2bfloat16(v);
    *hi = h;
    *lo = __float2bfloat16(v - __bfloat162float(h));
}

// ---------------- init ----------------
__global__ void k_init() {
    int i = blockIdx.x * blockDim.x + threadIdx.x;
    if (i < TS) d_table[i] = 0xFFFFFFFFu;
    if (i < NN) {
        d_m[i] = 0u; d_sum[i] = 0.f; d_used[i] = 0;
        d_cluster[i] = i; d_nscore[i] = 1.f; d_addsrc[i] = -1;
        d_deg[i] = 0.f; d_indeg[i] = 0;
        d_best[0][i] = ~0ull; d_best[1][i] = ~0ull;
    }
    if (i < BB * CC) { d_gmax[i] = 0.f; d_gsum[i] = 0.f; }
    if (i < BB) d_cnt[i] = 0.f;
    if (i == 0) { d_M = 0; g_arrive = 0u; d_lcnt[0] = 0; d_lcnt[1] = 0; }
}

// pack both weight sets TRANSPOSED [n][k] + split hi/lo (one launch)
__global__ void k_packw(const float* __restrict__ w10, const float* __restrict__ w11,
                        const float* __restrict__ w20, const float* __restrict__ w21) {
    int idx = blockIdx.x * blockDim.x + threadIdx.x;
    if (idx < ND * KP1) {
        int n = idx / KP1, k = idx % KP1;
        float v = 0.f;
        if (k < FIN) v = (n < CC) ? w10[k * CC + n] : w11[k * CC + (n - CC)];
        bf16split(v, &d_W1h[idx], &d_W1l[idx]);
    }
    if (idx < ND * CC) {
        int n = idx / CC, k = idx % CC;
        float v = (n < CC) ? w20[k * CC + n] : w21[k * CC + (n - CC)];
        bf16split(v, &d_W2h[idx], &d_W2l[idx]);
    }
}

// per-node dot products (1 warp / node; x rows are only 4B-aligned -> scalar)
__global__ void k_node_dots(const float* __restrict__ x, const float* __restrict__ pw) {
    int n = blockIdx.x * (blockDim.x / 32) + (threadIdx.x >> 5);
    if (n >= NN) return;
    int lane = threadIdx.x & 31;
    const float* xr = x + (size_t)n * FIN;
    float sa = 0.f, sb = 0.f;
    for (int f = lane; f < FIN; f += 32) {
        float xv = xr[f];
        sa += xv * pw[f];
        sb += xv * pw[FIN + f];
    }
    for (int o = 16; o; o >>= 1) {
        sa += __shfl_down_sync(0xFFFFFFFFu, sa, o);
        sb += __shfl_down_sync(0xFFFFFFFFu, sb, o);
    }
    if (!lane) { d_a[n] = sa; d_b[n] = sb; }
}

// ---------------- persistent matching (softmax + frontier rounds) --------
__device__ __forceinline__ void gridbar(unsigned nb, unsigned* gen) {
    __syncthreads();
    if (threadIdx.x == 0) {
        __threadfence();
        atomicAdd(&g_arrive, 1u);
        unsigned target = (*gen) * nb;
        while (*((volatile unsigned*)&g_arrive) < target) __nanosleep(32);
    }
    __syncthreads();
}

__global__ void __launch_bounds__(256) k_match(const int* __restrict__ ei,
                                               const float* __restrict__ pb) {
    const unsigned nb = gridDim.x;
    const int tid = blockIdx.x * blockDim.x + threadIdx.x;
    const int nthr = nb * blockDim.x;
    const int lane = threadIdx.x & 31;
    unsigned gen = 0;

    float pbv = pb[0];
    for (int k = tid; k < EE; k += nthr) {
        int u = ei[k], v = ei[EE + k];
        float e = d_a[u] + d_b[v] + pbv;
        d_e[k] = e;
        atomicMax(&d_m[v], fenc(e));
    }
    gen++; gridbar(nb, &gen);

    for (int k = tid; k < EE; k += nthr) {
        int v = ei[EE + k];
        float ex = expf(d_e[k] - fdec(d_m[v]));
        d_ex[k] = ex;
        atomicAdd(&d_sum[v], ex);
    }
    gen++; gridbar(nb, &gen);

    for (int r = 0; r < ROUNDS; r++) {
        int p = r & 1;
        for (int i = tid; i < NN; i += nthr) d_best[p ^ 1][i] = ~0ull;
        int total = (r == 0) ? EE : *((volatile int*)&d_lcnt[p ^ 1]);
        const int* src = d_list[p ^ 1];
        int* dst = d_list[p];
        int iters = (total + nthr - 1) / nthr;
        for (int j = 0; j < iters; j++) {
            int idx = tid + j * nthr;
            bool valid = idx < total;
            int k = 0, u = 0, v = 0;
            unsigned long long key = 0;
            bool want = false;
            if (valid) {
                k = (r == 0) ? idx : ((volatile const int*)src)[idx];
                u = ei[k]; v = ei[EE + k];
                int uu = *((volatile int*)&d_used[u]);
                int vv = *((volatile int*)&d_used[v]);
                if (!(uu | vv)) {
                    want = true;
                    if (r == 0) {
                        float s = d_ex[k] / d_sum[v] + 0.5f;
                        d_score[k] = s;
                        key = ((unsigned long long)(~__float_as_uint(s)) << 32) | (unsigned)k;
                        d_key[k] = key;
                    } else {
                        key = d_key[k];
                    }
                }
            }
            unsigned mask = __ballot_sync(0xFFFFFFFFu, want);
            if (mask) {
                int leader = __ffs(mask) - 1;
                int base = 0;
                if (lane == leader) base = atomicAdd(&d_lcnt[p], __popc(mask));
                base = __shfl_sync(0xFFFFFFFFu, base, leader);
                if (want) {
                    dst[base + __popc(mask & ((1u << lane) - 1))] = k;
                    atomicMin(&d_best[p][u], key);
                    if (v != u) atomicMin(&d_best[p][v], key);
                }
            }
        }
        gen++; gridbar(nb, &gen);
        int cnt = *((volatile int*)&d_lcnt[p]);
        if (cnt == 0) break;
        if (tid == 0) atomicExch(&d_lcnt[p ^ 1], 0);
        for (int idx = tid; idx < cnt; idx += nthr) {
            int k = ((volatile const int*)dst)[idx];
            int u = ei[k], v = ei[EE + k];
            unsigned long long key = d_key[k];
            unsigned long long bu = *((volatile unsigned long long*)&d_best[p][u]);
            unsigned long long bv = *((volatile unsigned long long*)&d_best[p][v]);
            if (key == bu && key == bv) {
                d_used[u] = 1; d_used[v] = 1;
                int rep = min(u, v), oth = max(u, v);
                d_cluster[u] = rep; d_cluster[v] = rep;
                d_nscore[rep] = d_score[k];
                d_addsrc[rep] = oth;
            }
        }
        gen++; gridbar(nb, &gen);
    }
}

// ---------------- valid-node compaction scan (single block) ----------------
__global__ void __launch_bounds__(1024) k_validscan() {
    __shared__ int ssum[1024];
    int t = threadIdx.x;
    int base = t * 32;
    unsigned flags = 0;
    int s = 0;
#pragma unroll
    for (int j = 0; j < 32; j++) {
        int ok = (d_cluster[base + j] == base + j) ? 1 : 0;
        flags |= ((unsigned)ok << j);
        s += ok;
    }
    ssum[t] = s;
    __syncthreads();
    for (int off = 1; off < 1024; off <<= 1) {
        int v = (t >= off) ? ssum[t - off] : 0;
        __syncthreads();
        ssum[t] += v;
        __syncthreads();
    }
    int ex = ssum[t] - s;
#pragma unroll
    for (int j = 0; j < 32; j++) {
        if ((flags >> j) & 1u) {
            d_cmap[base + j] = ex;
            d_nodes[ex] = base + j;
            ex++;
        }
    }
    if (t == 1023) {
        d_nvalid = ex;
        d_nvalid_pad = (ex + 127) & ~127;
    }
}

// pooled node features: one block (128 thr) per compact row; scalar x loads
__global__ void __launch_bounds__(128) k_pxsplit(const float* __restrict__ x) {
    int i = blockIdx.x, t = threadIdx.x;
    if (i >= d_nvalid_pad) return;
    __nv_bfloat16* rowh = d_Ah + (size_t)i * KP1;
    __nv_bfloat16* rowl = d_Al + (size_t)i * KP1;
    if (i >= d_nvalid) {  // zero padding rows
        for (int f = t * 4; f < KP1; f += 512) {
            *(ushort2*)(rowh + f) = make_ushort2(0, 0);
            *(ushort2*)(rowh + f + 2) = make_ushort2(0, 0);
            *(ushort2*)(rowl + f) = make_ushort2(0, 0);
            *(ushort2*)(rowl + f + 2) = make_ushort2(0, 0);
        }
        return;
    }
    int n = d_nodes[i];
    int o = d_addsrc[n];
    float sc = d_nscore[n];
    const float* xr = x + (size_t)n * FIN;
    const float* xo = (o >= 0 && o != n) ? x + (size_t)o * FIN : nullptr;
    // cols [0, 1024): 4 scalar loads per thread per iter (x is 4B-aligned only)
#pragma unroll 2
    for (int f4 = t * 4; f4 < 1024; f4 += 512) {
        float v0 = xr[f4 + 0], v1 = xr[f4 + 1], v2 = xr[f4 + 2], v3 = xr[f4 + 3];
        if (xo) {
            v0 += xo[f4 + 0]; v1 += xo[f4 + 1];
            v2 += xo[f4 + 2]; v3 += xo[f4 + 3];
        }
        v0 *= sc; v1 *= sc; v2 *= sc; v3 *= sc;
        __nv_bfloat16 h[4], l[4];
        bf16split(v0, &h[0], &l[0]);
        bf16split(v1, &h[1], &l[1]);
        bf16split(v2, &h[2], &l[2]);
        bf16split(v3, &h[3], &l[3]);
        *(ushort2*)(rowh + f4) = make_ushort2(__bfloat16_as_ushort(h[0]), __bfloat16_as_ushort(h[1]));
        *(ushort2*)(rowh + f4 + 2) = make_ushort2(__bfloat16_as_ushort(h[2]), __bfloat16_as_ushort(h[3]));
        *(ushort2*)(rowl + f4) = make_ushort2(__bfloat16_as_ushort(l[0]), __bfloat16_as_ushort(l[1]));
        *(ushort2*)(rowl + f4 + 2) = make_ushort2(__bfloat16_as_ushort(l[2]), __bfloat16_as_ushort(l[3]));
    }
    // cols [1024, KP1): col 1024 real, rest zero-pad
    if (t < 32) {
        int f = 1024 + t;
        float v = 0.f;
        if (f < FIN) {
            v = xr[f];
            if (xo) v += xo[f];
            v *= sc;
        }
        __nv_bfloat16 h, l;
        bf16split(v, &h, &l);
        rowh[f] = h;
        rowl[f] = l;
    }
}

// dedup coarsened edges (compact ids); out-degree (norm) + in-degree (CSR)
__global__ void k_dedup(const int* __restrict__ ei) {
    int k = blockIdx.x * blockDim.x + threadIdx.x;
    if (k >= EE) return;
    int cun = d_cluster[ei[k]], cvn = d_cluster[ei[EE + k]];
    if (cun == cvn) return;
    int cu = d_cmap[cun], cv = d_cmap[cvn];
    unsigned key = (unsigned)cu * (unsigned)NN + (unsigned)cv;
    unsigned slot = (key * 2654435761u) >> 14;
    slot &= (TS - 1);
    while (true) {
        unsigned prev = atomicCAS(&d_table[slot], 0xFFFFFFFFu, key);
        if (prev == 0xFFFFFFFFu) {
            int i = atomicAdd(&d_M, 1);
            d_cu[i] = cu; d_cv[i] = cv;
            atomicAdd(&d_deg[cu], 1.0f);
            atomicAdd(&d_indeg[cv], 1);
            return;
        }
        if (prev == key) return;
        slot = (slot + 1) & (TS - 1);
    }
}

// single-block exclusive scan of in-degrees + dis from deg
__global__ void __launch_bounds__(1024) k_scan() {
    __shared__ int ssum[1024];
    int t = threadIdx.x;
    int base = t * 32;
    int loc[32];
    int s = 0;
#pragma unroll
    for (int j = 0; j < 32; j++) { loc[j] = d_indeg[base + j]; s += loc[j]; }
    ssum[t] = s;
    __syncthreads();
    for (int off = 1; off < 1024; off <<= 1) {
        int v = (t >= off) ? ssum[t - off] : 0;
        __syncthreads();
        ssum[t] += v;
        __syncthreads();
    }
    int ex = ssum[t] - s;
#pragma unroll
    for (int j = 0; j < 32; j++) {
        d_off[base + j] = ex;
        d_fill[base + j] = ex;
        ex += loc[j];
        float d = d_deg[base + j];
        d_dis[base + j] = (d > 0.f) ? rsqrtf(d) : 0.f;
    }
    if (t == 1023) d_off[NN] = ex;
}

__global__ void k_csrfill() {
    int i = blockIdx.x * blockDim.x + threadIdx.x;
    if (i >= d_M) return;
    int pos = atomicAdd(&d_fill[d_cv[i]], 1);
    d_adj[pos] = d_cu[i];
}

// ---------------- tensor-core split-bf16 GEMM (128x256 tile, 3-stage) -----
__device__ __forceinline__ void ldsm_x4(unsigned& r0, unsigned& r1, unsigned& r2, unsigned& r3,
                                        unsigned addr) {
    asm volatile("ldmatrix.sync.aligned.m8n8.x4.shared.b16 {%0,%1,%2,%3}, [%4];\n"
                 : "=r"(r0), "=r"(r1), "=r"(r2), "=r"(r3) : "r"(addr));
}
__device__ __forceinline__ void ldsm_x2(unsigned& r0, unsigned& r1, unsigned addr) {
    asm volatile("ldmatrix.sync.aligned.m8n8.x2.shared.b16 {%0,%1}, [%2];\n"
                 : "=r"(r0), "=r"(r1) : "r"(addr));
}
__device__ __forceinline__ void mma_bf16(float* c, const unsigned* a, const unsigned* b) {
    asm volatile("mma.sync.aligned.m16n8k16.row.col.f32.bf16.bf16.f32 "
                 "{%0,%1,%2,%3},{%4,%5,%6,%7},{%8,%9},{%0,%1,%2,%3};\n"
                 : "+f"(c[0]), "+f"(c[1]), "+f"(c[2]), "+f"(c[3])
                 : "r"(a[0]), "r"(a[1]), "r"(a[2]), "r"(a[3]), "r"(b[0]), "r"(b[1]));
}
__device__ __forceinline__ void cpasync16(void* dst, const void* src) {
    unsigned d = (unsigned)__cvta_generic_to_shared(dst);
    asm volatile("cp.async.cg.shared.global [%0], [%1], 16;\n" :: "r"(d), "l"(src));
}

#define SKS 40                       // smem row stride (elems): 80B, 16B-aligned
#define TA (128 * SKS)               // A tile elems per array
#define TB (256 * SKS)               // B tile elems per array
#define STAGE_ELEMS (2 * TA + 2 * TB)
#define GSMEM (3 * STAGE_ELEMS * 2)  // 184320 bytes

__device__ __forceinline__ void g_load_stage(
    __nv_bfloat16* st, int t, int bm, int bn, int k0, int K,
    const __nv_bfloat16* Ah, const __nv_bfloat16* Al,
    const __nv_bfloat16* Bh, const __nv_bfloat16* Bl) {
#pragma unroll
    for (int it = 0; it < 2; it++) {
        int i = t + it * 256;
        int rr = i >> 2, cc8 = (i & 3) * 8;
        cpasync16(&st[0 * TA + rr * SKS + cc8], Ah + (size_t)(bm + rr) * K + k0 + cc8);
        cpasync16(&st[1 * TA + rr * SKS + cc8], Al + (size_t)(bm + rr) * K + k0 + cc8);
    }
#pragma unroll
    for (int it = 0; it < 4; it++) {
        int i = t + it * 256;
        int rr = i >> 2, cc8 = (i & 3) * 8;
        cpasync16(&st[2 * TA + rr * SKS + cc8], Bh + (size_t)(bn + rr) * K + k0 + cc8);
        cpasync16(&st[2 * TA + TB + rr * SKS + cc8], Bl + (size_t)(bn + rr) * K + k0 + cc8);
    }
}

__global__ __launch_bounds__(256, 1) void k_mma_gemm(
    const __nv_bfloat16* __restrict__ Ah, const __nv_bfloat16* __restrict__ Al,
    const __nv_bfloat16* __restrict__ Bh, const __nv_bfloat16* __restrict__ Bl,
    float* __restrict__ Cm, int K) {
    extern __shared__ __nv_bfloat16 smem[];
    const int bm = blockIdx.y * 128, bn = blockIdx.x * 256;
    if (bm >= d_nvalid_pad) return;
    const int t = threadIdx.x;
    const int warp = t >> 5, lane = t & 31;
    const int wm = warp & 1, wn = warp >> 1;          // 2 x 4 warp grid
    const int mrow0 = wm * 64, nrow0 = wn * 64;       // 64x64 per warp
    const int m4 = lane >> 3, r8 = lane & 7;
    const int mB = (lane >> 3) & 1;

    float acc[4][8][4];
#pragma unroll
    for (int mi = 0; mi < 4; mi++)
#pragma unroll
        for (int ni = 0; ni < 8; ni++)
#pragma unroll
            for (int r = 0; r < 4; r++) acc[mi][ni][r] = 0.f;

    const int KT = K / 32;
    g_load_stage(smem, t, bm, bn, 0, K, Ah, Al, Bh, Bl);
    asm volatile("cp.async.commit_group;\n" ::: "memory");
    g_load_stage(smem + STAGE_ELEMS, t, bm, bn, 32, K, Ah, Al, Bh, Bl);
    asm volatile("cp.async.commit_group;\n" ::: "memory");

    for (int kt = 0; kt < KT; kt++) {
        if (kt + 2 < KT)
            g_load_stage(smem + ((kt + 2) % 3) * STAGE_ELEMS, t, bm, bn, (kt + 2) * 32, K,
                         Ah, Al, Bh, Bl);
        asm volatile("cp.async.commit_group;\n" ::: "memory");
        asm volatile("cp.async.wait_group 2;\n" ::: "memory");
        __syncthreads();

        __nv_bfloat16* st = smem + (kt % 3) * STAGE_ELEMS;
        __nv_bfloat16* sAh = st;
        __nv_bfloat16* sAl = st + TA;
        __nv_bfloat16* sBh = st + 2 * TA;
        __nv_bfloat16* sBl = st + 2 * TA + TB;

#pragma unroll
        for (int ks = 0; ks < 2; ks++) {
            unsigned ah[4][4], al[4][4], bh[8][2], bl[8][2];
#pragma unroll
            for (int mi = 0; mi < 4; mi++) {
                int rr = mrow0 + mi * 16 + (m4 & 1) * 8 + r8;
                int col = (m4 >> 1) * 8 + ks * 16;
                ldsm_x4(ah[mi][0], ah[mi][1], ah[mi][2], ah[mi][3],
                        (unsigned)__cvta_generic_to_shared(&sAh[rr * SKS + col]));
                ldsm_x4(al[mi][0], al[mi][1], al[mi][2], al[mi][3],
                        (unsigned)__cvta_generic_to_shared(&sAl[rr * SKS + col]));
            }
#pragma unroll
            for (int ni = 0; ni < 8; ni++) {
                int rr = nrow0 + ni * 8 + r8;
                int col = mB * 8 + ks * 16;
                ldsm_x2(bh[ni][0], bh[ni][1],
                        (unsigned)__cvta_generic_to_shared(&sBh[rr * SKS + col]));
                ldsm_x2(bl[ni][0], bl[ni][1],
                        (unsigned)__cvta_generic_to_shared(&sBl[rr * SKS + col]));
            }
#pragma unroll
            for (int mi = 0; mi < 4; mi++)
#pragma unroll
                for (int ni = 0; ni < 8; ni++) {
                    mma_bf16(acc[mi][ni], ah[mi], bh[ni]);
                    mma_bf16(acc[mi][ni], ah[mi], bl[ni]);
                    mma_bf16(acc[mi][ni], al[mi], bh[ni]);
                }
        }
        __syncthreads();
    }
#pragma unroll
    for (int mi = 0; mi < 4; mi++) {
        int r0 = bm + mrow0 + mi * 16 + (lane >> 2);
#pragma unroll
        for (int ni = 0; ni < 8; ni++) {
            int c0 = bn + nrow0 + ni * 8 + (lane & 3) * 2;
            *(float2*)&Cm[(size_t)r0 * ND + c0] = make_float2(acc[mi][ni][0], acc[mi][ni][1]);
            *(float2*)&Cm[(size_t)(r0 + 8) * ND + c0] = make_float2(acc[mi][ni][2], acc[mi][ni][3]);
        }
    }
}

// ---------------- CSR gather + fused epilogue (compact rows) --------------
__device__ __forceinline__ unsigned packbf2(__nv_bfloat16 x, __nv_bfloat16 y) {
    return (unsigned)__bfloat16_as_ushort(x) | ((unsigned)__bfloat16_as_ushort(y) << 16);
}

__global__ void __launch_bounds__(128) k_gather1(const float* __restrict__ Y,
                                                 const float* __restrict__ bias,
                                                 const float* __restrict__ bn) {
    int i = blockIdx.x, t = threadIdx.x;
    if (i >= d_nvalid_pad) return;
    int c = t * 4;
    if (i >= d_nvalid) {
        *(uint2*)(d_H1h + (size_t)i * CC + c) = make_uint2(0u, 0u);
        *(uint2*)(d_H1l + (size_t)i * CC + c) = make_uint2(0u, 0u);
        return;
    }
    float4 y0 = *(const float4*)(Y + (size_t)i * ND + c);
    float a0 = y0.x, a1 = y0.y, a2 = y0.z, a3 = y0.w;
    float disv = d_dis[i];
    int e = d_off[i], end = d_off[i + 1];
    for (; e + 1 < end; e += 2) {
        int cu0 = d_adj[e], cu1 = d_adj[e + 1];
        float nr0 = -disv * d_dis[cu0];
        float nr1 = -disv * d_dis[cu1];
        float4 ya = *(const float4*)(Y + (size_t)cu0 * ND + CC + c);
        float4 yb = *(const float4*)(Y + (size_t)cu1 * ND + CC + c);
        a0 += nr0 * ya.x + nr1 * yb.x;
        a1 += nr0 * ya.y + nr1 * yb.y;
        a2 += nr0 * ya.z + nr1 * yb.z;
        a3 += nr0 * ya.w + nr1 * yb.w;
    }
    if (e < end) {
        int cu = d_adj[e];
        float nrm = -disv * d_dis[cu];
        float4 y = *(const float4*)(Y + (size_t)cu * ND + CC + c);
        a0 += nrm * y.x; a1 += nrm * y.y; a2 += nrm * y.z; a3 += nrm * y.w;
    }
    float v[4] = {a0, a1, a2, a3};
    __nv_bfloat16 h[4], l[4];
#pragma unroll
    for (int j = 0; j < 4; j++) {
        float val = v[j] + bias[c + j];
        val = (val - bn[2 * CC + c + j]) * rsqrtf(bn[3 * CC + c + j] + 1e-5f) * bn[c + j]
              + bn[CC + c + j];
        val = fmaxf(val, 0.f);
        bf16split(val, &h[j], &l[j]);
    }
    *(uint2*)(d_H1h + (size_t)i * CC + c) = make_uint2(packbf2(h[0], h[1]), packbf2(h[2], h[3]));
    *(uint2*)(d_H1l + (size_t)i * CC + c) = make_uint2(packbf2(l[0], l[1]), packbf2(l[2], l[3]));
}

__global__ void __launch_bounds__(128) k_gather2(const float* __restrict__ Y,
                                                 const float* __restrict__ bias,
                                                 const float* __restrict__ bn,
                                                 float* __restrict__ H) {
    int i = blockIdx.x, t = threadIdx.x;
    if (i >= d_nvalid) return;
    int c = t * 4;
    float4 y0 = *(const float4*)(Y + (size_t)i * ND + c);
    float a0 = y0.x, a1 = y0.y, a2 = y0.z, a3 = y0.w;
    float disv = d_dis[i];
    int e = d_off[i], end = d_off[i + 1];
    for (; e + 1 < end; e += 2) {
        int cu0 = d_adj[e], cu1 = d_adj[e + 1];
        float nr0 = -disv * d_dis[cu0];
        float nr1 = -disv * d_dis[cu1];
        float4 ya = *(const float4*)(Y + (size_t)cu0 * ND + CC + c);
        float4 yb = *(const float4*)(Y + (size_t)cu1 * ND + CC + c);
        a0 += nr0 * ya.x + nr1 * yb.x;
        a1 += nr0 * ya.y + nr1 * yb.y;
        a2 += nr0 * ya.z + nr1 * yb.z;
        a3 += nr0 * ya.w + nr1 * yb.w;
    }
    if (e < end) {
        int cu = d_adj[e];
        float nrm = -disv * d_dis[cu];
        float4 y = *(const float4*)(Y + (size_t)cu * ND + CC + c);
        a0 += nrm * y.x; a1 += nrm * y.y; a2 += nrm * y.z; a3 += nrm * y.w;
    }
    float v[4] = {a0, a1, a2, a3};
    float o[4];
#pragma unroll
    for (int j = 0; j < 4; j++) {
        float val = v[j] + bias[c + j];
        val = (val - bn[2 * CC + c + j]) * rsqrtf(bn[3 * CC + c + j] + 1e-5f) * bn[c + j]
              + bn[CC + c + j];
        o[j] = fmaxf(val, 0.f);
    }
    *(float4*)(H + (size_t)i * CC + c) = make_float4(o[0], o[1], o[2], o[3]);
}

// per-graph max+mean over valid nodes (H in compact rows)
__global__ void k_pool(const float* __restrict__ H, const int* __restrict__ batch) {
    __shared__ int sb[64];
    __shared__ int scm[64];
    __shared__ unsigned char sv[64];
    int base = blockIdx.x * 64;
    int t = threadIdx.x;
    if (t < 64) {
        int n = base + t;
        sb[t] = batch[n];
        bool val = (d_cluster[n] == n);
        sv[t] = val ? 1 : 0;
        scm[t] = val ? d_cmap[n] : 0;
    }
    __syncthreads();
    int c0 = t, c1 = t + 256;
    float mx0 = 0.f, mx1 = 0.f, s0 = 0.f, s1 = 0.f;
    int cnt = 0, curb = -1;
    for (int i = 0; i < 64; i++) {
        int b = sb[i];
        if (b != curb) {
            if (curb >= 0) {
                atomicMax((unsigned*)&d_gmax[curb * CC + c0], __float_as_uint(mx0));
                atomicMax((unsigned*)&d_gmax[curb * CC + c1], __float_as_uint(mx1));
                atomicAdd(&d_gsum[curb * CC + c0], s0);
                atomicAdd(&d_gsum[curb * CC + c1], s1);
                if (t == 0) atomicAdd(&d_cnt[curb], (float)cnt);
            }
            curb = b; mx0 = mx1 = s0 = s1 = 0.f; cnt = 0;
        }
        if (sv[i]) {
            const float* hr = H + (size_t)scm[i] * CC;
            float h0 = hr[c0], h1 = hr[c1];
            mx0 = fmaxf(mx0, h0); mx1 = fmaxf(mx1, h1);
            s0 += h0; s1 += h1; cnt++;
        }
    }
    if (curb >= 0) {
        atomicMax((unsigned*)&d_gmax[curb * CC + c0], __float_as_uint(mx0));
        atomicMax((unsigned*)&d_gmax[curb * CC + c1], __float_as_uint(mx1));
        atomicAdd(&d_gsum[curb * CC + c0], s0);
        atomicAdd(&d_gsum[curb * CC + c1], s1);
        if (t == 0) atomicAdd(&d_cnt[curb], (float)cnt);
    }
}

__global__ void k_readout(const float* __restrict__ l1w, const float* __restrict__ l1b,
                          const float* __restrict__ l2w, const float* __restrict__ l2b,
                          const float* __restrict__ l3w, const float* __restrict__ l3b,
                          const float* __restrict__ bn3, const float* __restrict__ bn4,
                          float* __restrict__ out) {
    int b = blockIdx.x, t = threadIdx.x;
    __shared__ float g[1024], g1[512], g2[256], zz[4];
    float cn = fmaxf(d_cnt[b], 1.f);
    g[t] = d_gmax[b * CC + t];
    g[CC + t] = d_gsum[b * CC + t] / cn;
    __syncthreads();
    {
        float acc = l1b[t];
        for (int k = 0; k < 1024; k++) acc += g[k] * l1w[k * 512 + t];
        acc = (acc - bn3[1024 + t]) * rsqrtf(bn3[1536 + t] + 1e-5f) * bn3[t] + bn3[512 + t];
        g1[t] = fmaxf(acc, 0.f);
    }
    __syncthreads();
    if (t < 256) {
        float acc = l2b[t];
        for (int k = 0; k < 512; k++) acc += g1[k] * l2w[k * 256 + t];
        acc = (acc - bn4[512 + t]) * rsqrtf(bn4[768 + t] + 1e-5f) * bn4[t] + bn4[256 + t];
        acc = fmaxf(acc, 0.f);
        g2[t] = acc;
        out[32 + b * 256 + t] = acc;
    }
    __syncthreads();
    if (t < 4) {
        float acc = l3b[t];
        for (int k = 0; k < 256; k++) acc += g2[k] * l3w[k * 4 + t];
        zz[t] = fmaxf(acc, 0.f);
    }
    __syncthreads();
    if (t < 4) {
        float m = fmaxf(fmaxf(zz[0], zz[1]), fmaxf(zz[2], zz[3]));
        float s = expf(zz[0] - m) + expf(zz[1] - m) + expf(zz[2] - m) + expf(zz[3] - m);
        out[b * 4 + t] = zz[t] - m - logf(s);
    }
}

extern "C" void kernel_launch(void* const* d_in, const int* in_sizes, int n_in,
                              void* d_out, int out_size) {
    const float* x      = (const float*)d_in[0];
    const int*   ei     = (const int*)d_in[1];
    const int*   batch  = (const int*)d_in[2];
    const float* pool_w = (const float*)d_in[3];
    const float* pool_b = (const float*)d_in[4];
    const float* c1w0   = (const float*)d_in[5];
    const float* c1w1   = (const float*)d_in[6];
    const float* c1b    = (const float*)d_in[7];
    const float* c2w0   = (const float*)d_in[8];
    const float* c2w1   = (const float*)d_in[9];
    const float* c2b    = (const float*)d_in[10];
    const float* bn1    = (const float*)d_in[11];
    const float* bn2    = (const float*)d_in[12];
    const float* bn3    = (const float*)d_in[13];
    const float* bn4    = (const float*)d_in[14];
    const float* l1w    = (const float*)d_in[15];
    const float* l1b    = (const float*)d_in[16];
    const float* l2w    = (const float*)d_in[17];
    const float* l2b    = (const float*)d_in[18];
    const float* l3w    = (const float*)d_in[19];
    const float* l3b    = (const float*)d_in[20];
    float* out = (float*)d_out;

    __nv_bfloat16 *p_Ah, *p_Al, *p_W1h, *p_W1l, *p_W2h, *p_W2l, *p_H1h, *p_H1l;
    float *p_Y, *p_H2;
    cudaGetSymbolAddress((void**)&p_Ah, d_Ah);
    cudaGetSymbolAddress((void**)&p_Al, d_Al);
    cudaGetSymbolAddress((void**)&p_W1h, d_W1h);
    cudaGetSymbolAddress((void**)&p_W1l, d_W1l);
    cudaGetSymbolAddress((void**)&p_W2h, d_W2h);
    cudaGetSymbolAddress((void**)&p_W2l, d_W2l);
    cudaGetSymbolAddress((void**)&p_H1h, d_H1h);
    cudaGetSymbolAddress((void**)&p_H1l, d_H1l);
    cudaGetSymbolAddress((void**)&p_Y, d_Y);
    cudaGetSymbolAddress((void**)&p_H2, d_H2);

    static int smem_set = 0;
    if (!smem_set) {
        cudaFuncSetAttribute(k_mma_gemm, cudaFuncAttributeMaxDynamicSharedMemorySize, GSMEM);
        smem_set = 1;
    }

    k_init<<<TS / 256, 256>>>();
    k_packw<<<(ND * KP1 + 255) / 256, 256>>>(c1w0, c1w1, c2w0, c2w1);
    k_node_dots<<<NN / 8, 256>>>(x, pool_w);

    k_match<<<MBLK, 256>>>(ei, pool_b);
    k_validscan<<<1, 1024>>>();

    k_pxsplit<<<NN, 128>>>(x);
    k_dedup<<<EE / 256, 256>>>(ei);
    k_scan<<<1, 1024>>>();
    k_csrfill<<<EE / 256, 256>>>();

    // conv1 (compact rows): [M,1056] x [1056,1024]
    k_mma_gemm<<<dim3(ND / 256, NN / 128), 256, GSMEM>>>(p_Ah, p_Al, p_W1h, p_W1l, p_Y, KP1);
    k_gather1<<<NN, 128>>>(p_Y, c1b, bn1);

    // conv2 (compact rows): [M,512] x [512,1024]
    k_mma_gemm<<<dim3(ND / 256, NN / 128), 256, GSMEM>>>(p_H1h, p_H1l, p_W2h, p_W2l, p_Y, CC);
    k_gather2<<<NN, 128>>>(p_Y, c2b, bn2, p_H2);

    // pooling + readout
    k_pool<<<NN / 64, 256>>>(p_H2, batch);
    k_readout<<<BB, 512>>>(l1w, l1b, l2w, l2b, l3w, l3b, bn3, bn4, out);
}

// round 17
// speedup vs baseline: 1.2726x; 1.1352x over previous
#include <cuda_runtime.h>
#include <cuda_bf16.h>
#include <math.h>

#define NN 32768
#define EE 131072
#define BB 8
#define FIN 1025
#define KP1 1056        // K padded (multiple of 32)
#define CC 512
#define ND 1024
#define TS (1<<18)
#define ROUNDS 96
#define MBLK 148

// ---------------- device scratch (static, no allocs) ----------------
__device__ float d_a[NN], d_b[NN];
__device__ float d_e[EE], d_ex[EE], d_score[EE];
__device__ unsigned d_m[NN];
__device__ float d_sum[NN];
__device__ unsigned long long d_key[EE];
__device__ int d_used[NN];
__device__ unsigned long long d_best[2][NN];
__device__ int d_list[2][EE];
__device__ int d_lcnt[2];
__device__ unsigned g_arrive;
__device__ int d_cluster[NN];
__device__ float d_nscore[NN];
__device__ int d_addsrc[NN];
__device__ unsigned d_table[TS];
__device__ int d_M;
__device__ int d_cu[EE], d_cv[EE];       // compact indices
__device__ float d_deg[NN], d_dis[NN];   // compact indexed
__device__ int d_indeg[NN];              // compact indexed
__device__ int d_off[NN + 1];
__device__ int d_fill[NN];
__device__ int d_adj[EE];
__device__ int d_nvalid, d_nvalid_pad;
__device__ int d_cmap[NN];               // node -> compact
__device__ int d_nodes[NN];              // compact -> node

__device__ __nv_bfloat16 d_Ah[(size_t)NN * KP1];
__device__ __nv_bfloat16 d_Al[(size_t)NN * KP1];
__device__ __nv_bfloat16 d_W1h[(size_t)ND * KP1];
__device__ __nv_bfloat16 d_W1l[(size_t)ND * KP1];
__device__ __nv_bfloat16 d_W2h[(size_t)ND * CC];
__device__ __nv_bfloat16 d_W2l[(size_t)ND * CC];
__device__ __nv_bfloat16 d_H1h[(size_t)NN * CC];
__device__ __nv_bfloat16 d_H1l[(size_t)NN * CC];
__device__ float d_Y[(size_t)NN * ND];
__device__ float d_H2[(size_t)NN * CC];
__device__ float d_gmax[BB * CC], d_gsum[BB * CC], d_cnt[BB];

__device__ __forceinline__ unsigned fenc(float f) {
    unsigned u = __float_as_uint(f);
    return (u & 0x80000000u) ? ~u : (u | 0x80000000u);
}
__device__ __forceinline__ float fdec(unsigned u) {
    return (u & 0x80000000u) ? __uint_as_float(u ^ 0x80000000u)
                             : __uint_as_float(~u);
}
__device__ __forceinline__ void bf16split(float v, __nv_bfloat16* hi, __nv_bfloat16* lo) {
    __nv_bfloat16 h = __float2bfloat16(v);
    *hi = h;
    *lo = __float2bfloat16(v - __bfloat162float(h));
}

// ---------------- init ----------------
__global__ void k_init() {
    int i = blockIdx.x * blockDim.x + threadIdx.x;
    if (i < TS) d_table[i] = 0xFFFFFFFFu;
    if (i < NN) {
        d_m[i] = 0u; d_sum[i] = 0.f; d_used[i] = 0;
        d_cluster[i] = i; d_nscore[i] = 1.f; d_addsrc[i] = -1;
        d_deg[i] = 0.f; d_indeg[i] = 0;
        d_best[0][i] = ~0ull; d_best[1][i] = ~0ull;
    }
    if (i < BB * CC) { d_gmax[i] = 0.f; d_gsum[i] = 0.f; }
    if (i < BB) d_cnt[i] = 0.f;
    if (i == 0) { d_M = 0; g_arrive = 0u; d_lcnt[0] = 0; d_lcnt[1] = 0; }
}

// pack both weight sets TRANSPOSED [n][k] + split hi/lo (one launch)
__global__ void k_packw(const float* __restrict__ w10, const float* __restrict__ w11,
                        const float* __restrict__ w20, const float* __restrict__ w21) {
    int idx = blockIdx.x * blockDim.x + threadIdx.x;
    if (idx < ND * KP1) {
        int n = idx / KP1, k = idx % KP1;
        float v = 0.f;
        if (k < FIN) v = (n < CC) ? w10[k * CC + n] : w11[k * CC + (n - CC)];
        bf16split(v, &d_W1h[idx], &d_W1l[idx]);
    }
    if (idx < ND * CC) {
        int n = idx / CC, k = idx % CC;
        float v = (n < CC) ? w20[k * CC + n] : w21[k * CC + (n - CC)];
        bf16split(v, &d_W2h[idx], &d_W2l[idx]);
    }
}

// per-node dot products (1 warp / node; x rows are only 4B-aligned -> scalar)
__global__ void k_node_dots(const float* __restrict__ x, const float* __restrict__ pw) {
    int n = blockIdx.x * (blockDim.x / 32) + (threadIdx.x >> 5);
    if (n >= NN) return;
    int lane = threadIdx.x & 31;
    const float* xr = x + (size_t)n * FIN;
    float sa = 0.f, sb = 0.f;
    for (int f = lane; f < FIN; f += 32) {
        float xv = xr[f];
        sa += xv * pw[f];
        sb += xv * pw[FIN + f];
    }
    for (int o = 16; o; o >>= 1) {
        sa += __shfl_down_sync(0xFFFFFFFFu, sa, o);
        sb += __shfl_down_sync(0xFFFFFFFFu, sb, o);
    }
    if (!lane) { d_a[n] = sa; d_b[n] = sb; }
}

// ---------------- persistent matching (softmax + frontier rounds) --------
__device__ __forceinline__ void gridbar(unsigned nb, unsigned* gen) {
    __syncthreads();
    if (threadIdx.x == 0) {
        __threadfence();
        atomicAdd(&g_arrive, 1u);
        unsigned target = (*gen) * nb;
        while (*((volatile unsigned*)&g_arrive) < target) __nanosleep(32);
    }
    __syncthreads();
}

__global__ void __launch_bounds__(256) k_match(const int* __restrict__ ei,
                                               const float* __restrict__ pb) {
    const unsigned nb = gridDim.x;
    const int tid = blockIdx.x * blockDim.x + threadIdx.x;
    const int nthr = nb * blockDim.x;
    const int lane = threadIdx.x & 31;
    unsigned gen = 0;

    float pbv = pb[0];
    for (int k = tid; k < EE; k += nthr) {
        int u = ei[k], v = ei[EE + k];
        float e = d_a[u] + d_b[v] + pbv;
        d_e[k] = e;
        atomicMax(&d_m[v], fenc(e));
    }
    gen++; gridbar(nb, &gen);

    for (int k = tid; k < EE; k += nthr) {
        int v = ei[EE + k];
        float ex = expf(d_e[k] - fdec(d_m[v]));
        d_ex[k] = ex;
        atomicAdd(&d_sum[v], ex);
    }
    gen++; gridbar(nb, &gen);

    for (int r = 0; r < ROUNDS; r++) {
        int p = r & 1;
        for (int i = tid; i < NN; i += nthr) d_best[p ^ 1][i] = ~0ull;
        int total = (r == 0) ? EE : *((volatile int*)&d_lcnt[p ^ 1]);
        const int* src = d_list[p ^ 1];
        int* dst = d_list[p];
        int iters = (total + nthr - 1) / nthr;
        for (int j = 0; j < iters; j++) {
            int idx = tid + j * nthr;
            bool valid = idx < total;
            int k = 0, u = 0, v = 0;
            unsigned long long key = 0;
            bool want = false;
            if (valid) {
                k = (r == 0) ? idx : ((volatile const int*)src)[idx];
                u = ei[k]; v = ei[EE + k];
                int uu = *((volatile int*)&d_used[u]);
                int vv = *((volatile int*)&d_used[v]);
                if (!(uu | vv)) {
                    want = true;
                    if (r == 0) {
                        float s = d_ex[k] / d_sum[v] + 0.5f;
                        d_score[k] = s;
                        key = ((unsigned long long)(~__float_as_uint(s)) << 32) | (unsigned)k;
                        d_key[k] = key;
                    } else {
                        key = d_key[k];
                    }
                }
            }
            unsigned mask = __ballot_sync(0xFFFFFFFFu, want);
            if (mask) {
                int leader = __ffs(mask) - 1;
                int base = 0;
                if (lane == leader) base = atomicAdd(&d_lcnt[p], __popc(mask));
                base = __shfl_sync(0xFFFFFFFFu, base, leader);
                if (want) {
                    dst[base + __popc(mask & ((1u << lane) - 1))] = k;
                    atomicMin(&d_best[p][u], key);
                    if (v != u) atomicMin(&d_best[p][v], key);
                }
            }
        }
        gen++; gridbar(nb, &gen);
        int cnt = *((volatile int*)&d_lcnt[p]);
        if (cnt == 0) break;
        if (tid == 0) atomicExch(&d_lcnt[p ^ 1], 0);
        for (int idx = tid; idx < cnt; idx += nthr) {
            int k = ((volatile const int*)dst)[idx];
            int u = ei[k], v = ei[EE + k];
            unsigned long long key = d_key[k];
            unsigned long long bu = *((volatile unsigned long long*)&d_best[p][u]);
            unsigned long long bv = *((volatile unsigned long long*)&d_best[p][v]);
            if (key == bu && key == bv) {
                d_used[u] = 1; d_used[v] = 1;
                int rep = min(u, v), oth = max(u, v);
                d_cluster[u] = rep; d_cluster[v] = rep;
                d_nscore[rep] = d_score[k];
                d_addsrc[rep] = oth;
            }
        }
        gen++; gridbar(nb, &gen);
    }
}

// ---------------- valid-node compaction scan (single block) ----------------
__global__ void __launch_bounds__(1024) k_validscan() {
    __shared__ int ssum[1024];
    int t = threadIdx.x;
    int base = t * 32;
    unsigned flags = 0;
    int s = 0;
#pragma unroll
    for (int j = 0; j < 32; j++) {
        int ok = (d_cluster[base + j] == base + j) ? 1 : 0;
        flags |= ((unsigned)ok << j);
        s += ok;
    }
    ssum[t] = s;
    __syncthreads();
    for (int off = 1; off < 1024; off <<= 1) {
        int v = (t >= off) ? ssum[t - off] : 0;
        __syncthreads();
        ssum[t] += v;
        __syncthreads();
    }
    int ex = ssum[t] - s;
#pragma unroll
    for (int j = 0; j < 32; j++) {
        if ((flags >> j) & 1u) {
            d_cmap[base + j] = ex;
            d_nodes[ex] = base + j;
            ex++;
        }
    }
    if (t == 1023) {
        d_nvalid = ex;
        d_nvalid_pad = (ex + 127) & ~127;
    }
}

// pooled node features: one block (128 thr) per compact row; scalar x loads
__global__ void __launch_bounds__(128) k_pxsplit(const float* __restrict__ x) {
    int i = blockIdx.x, t = threadIdx.x;
    if (i >= d_nvalid_pad) return;
    __nv_bfloat16* rowh = d_Ah + (size_t)i * KP1;
    __nv_bfloat16* rowl = d_Al + (size_t)i * KP1;
    if (i >= d_nvalid) {  // zero padding rows
        for (int f = t * 4; f < KP1; f += 512) {
            *(ushort2*)(rowh + f) = make_ushort2(0, 0);
            *(ushort2*)(rowh + f + 2) = make_ushort2(0, 0);
            *(ushort2*)(rowl + f) = make_ushort2(0, 0);
            *(ushort2*)(rowl + f + 2) = make_ushort2(0, 0);
        }
        return;
    }
    int n = d_nodes[i];
    int o = d_addsrc[n];
    float sc = d_nscore[n];
    const float* xr = x + (size_t)n * FIN;
    const float* xo = (o >= 0 && o != n) ? x + (size_t)o * FIN : nullptr;
#pragma unroll 2
    for (int f4 = t * 4; f4 < 1024; f4 += 512) {
        float v0 = xr[f4 + 0], v1 = xr[f4 + 1], v2 = xr[f4 + 2], v3 = xr[f4 + 3];
        if (xo) {
            v0 += xo[f4 + 0]; v1 += xo[f4 + 1];
            v2 += xo[f4 + 2]; v3 += xo[f4 + 3];
        }
        v0 *= sc; v1 *= sc; v2 *= sc; v3 *= sc;
        __nv_bfloat16 h[4], l[4];
        bf16split(v0, &h[0], &l[0]);
        bf16split(v1, &h[1], &l[1]);
        bf16split(v2, &h[2], &l[2]);
        bf16split(v3, &h[3], &l[3]);
        *(ushort2*)(rowh + f4) = make_ushort2(__bfloat16_as_ushort(h[0]), __bfloat16_as_ushort(h[1]));
        *(ushort2*)(rowh + f4 + 2) = make_ushort2(__bfloat16_as_ushort(h[2]), __bfloat16_as_ushort(h[3]));
        *(ushort2*)(rowl + f4) = make_ushort2(__bfloat16_as_ushort(l[0]), __bfloat16_as_ushort(l[1]));
        *(ushort2*)(rowl + f4 + 2) = make_ushort2(__bfloat16_as_ushort(l[2]), __bfloat16_as_ushort(l[3]));
    }
    if (t < 32) {
        int f = 1024 + t;
        float v = 0.f;
        if (f < FIN) {
            v = xr[f];
            if (xo) v += xo[f];
            v *= sc;
        }
        __nv_bfloat16 h, l;
        bf16split(v, &h, &l);
        rowh[f] = h;
        rowl[f] = l;
    }
}

// dedup coarsened edges (compact ids); out-degree (norm) + in-degree (CSR)
__global__ void k_dedup(const int* __restrict__ ei) {
    int k = blockIdx.x * blockDim.x + threadIdx.x;
    if (k >= EE) return;
    int cun = d_cluster[ei[k]], cvn = d_cluster[ei[EE + k]];
    if (cun == cvn) return;
    int cu = d_cmap[cun], cv = d_cmap[cvn];
    unsigned key = (unsigned)cu * (unsigned)NN + (unsigned)cv;
    unsigned slot = (key * 2654435761u) >> 14;
    slot &= (TS - 1);
    while (true) {
        unsigned prev = atomicCAS(&d_table[slot], 0xFFFFFFFFu, key);
        if (prev == 0xFFFFFFFFu) {
            int i = atomicAdd(&d_M, 1);
            d_cu[i] = cu; d_cv[i] = cv;
            atomicAdd(&d_deg[cu], 1.0f);
            atomicAdd(&d_indeg[cv], 1);
            return;
        }
        if (prev == key) return;
        slot = (slot + 1) & (TS - 1);
    }
}

// single-block exclusive scan of in-degrees + dis from deg
__global__ void __launch_bounds__(1024) k_scan() {
    __shared__ int ssum[1024];
    int t = threadIdx.x;
    int base = t * 32;
    int loc[32];
    int s = 0;
#pragma unroll
    for (int j = 0; j < 32; j++) { loc[j] = d_indeg[base + j]; s += loc[j]; }
    ssum[t] = s;
    __syncthreads();
    for (int off = 1; off < 1024; off <<= 1) {
        int v = (t >= off) ? ssum[t - off] : 0;
        __syncthreads();
        ssum[t] += v;
        __syncthreads();
    }
    int ex = ssum[t] - s;
#pragma unroll
    for (int j = 0; j < 32; j++) {
        d_off[base + j] = ex;
        d_fill[base + j] = ex;
        ex += loc[j];
        float d = d_deg[base + j];
        d_dis[base + j] = (d > 0.f) ? rsqrtf(d) : 0.f;
    }
    if (t == 1023) d_off[NN] = ex;
}

__global__ void k_csrfill() {
    int i = blockIdx.x * blockDim.x + threadIdx.x;
    if (i >= d_M) return;
    int pos = atomicAdd(&d_fill[d_cv[i]], 1);
    d_adj[pos] = d_cu[i];
}

// ---------------- tensor-core split-bf16 GEMM (128x256 tile, 3-stage) -----
__device__ __forceinline__ void ldsm_x4(unsigned& r0, unsigned& r1, unsigned& r2, unsigned& r3,
                                        unsigned addr) {
    asm volatile("ldmatrix.sync.aligned.m8n8.x4.shared.b16 {%0,%1,%2,%3}, [%4];\n"
                 : "=r"(r0), "=r"(r1), "=r"(r2), "=r"(r3) : "r"(addr));
}
__device__ __forceinline__ void ldsm_x2(unsigned& r0, unsigned& r1, unsigned addr) {
    asm volatile("ldmatrix.sync.aligned.m8n8.x2.shared.b16 {%0,%1}, [%2];\n"
                 : "=r"(r0), "=r"(r1) : "r"(addr));
}
__device__ __forceinline__ void mma_bf16(float* c, const unsigned* a, const unsigned* b) {
    asm volatile("mma.sync.aligned.m16n8k16.row.col.f32.bf16.bf16.f32 "
                 "{%0,%1,%2,%3},{%4,%5,%6,%7},{%8,%9},{%0,%1,%2,%3};\n"
                 : "+f"(c[0]), "+f"(c[1]), "+f"(c[2]), "+f"(c[3])
                 : "r"(a[0]), "r"(a[1]), "r"(a[2]), "r"(a[3]), "r"(b[0]), "r"(b[1]));
}
__device__ __forceinline__ void cpasync16(void* dst, const void* src) {
    unsigned d = (unsigned)__cvta_generic_to_shared(dst);
    asm volatile("cp.async.cg.shared.global [%0], [%1], 16;\n" :: "r"(d), "l"(src));
}

#define SKS 40                       // smem row stride (elems): 80B, 16B-aligned
#define TA (128 * SKS)               // A tile elems per array
#define TB (256 * SKS)               // B tile elems per array
#define STAGE_ELEMS (2 * TA + 2 * TB)
#define GSMEM (3 * STAGE_ELEMS * 2)  // 184320 bytes

__device__ __forceinline__ void g_load_stage(
    __nv_bfloat16* st, int t, int bm, int bn, int k0, int K,
    const __nv_bfloat16* Ah, const __nv_bfloat16* Al,
    const __nv_bfloat16* Bh, const __nv_bfloat16* Bl) {
#pragma unroll
    for (int it = 0; it < 2; it++) {
        int i = t + it * 256;
        int rr = i >> 2, cc8 = (i & 3) * 8;
        cpasync16(&st[0 * TA + rr * SKS + cc8], Ah + (size_t)(bm + rr) * K + k0 + cc8);
        cpasync16(&st[1 * TA + rr * SKS + cc8], Al + (size_t)(bm + rr) * K + k0 + cc8);
    }
#pragma unroll
    for (int it = 0; it < 4; it++) {
        int i = t + it * 256;
        int rr = i >> 2, cc8 = (i & 3) * 8;
        cpasync16(&st[2 * TA + rr * SKS + cc8], Bh + (size_t)(bn + rr) * K + k0 + cc8);
        cpasync16(&st[2 * TA + TB + rr * SKS + cc8], Bl + (size_t)(bn + rr) * K + k0 + cc8);
    }
}

__global__ __launch_bounds__(256, 1) void k_mma_gemm(
    const __nv_bfloat16* __restrict__ Ah, const __nv_bfloat16* __restrict__ Al,
    const __nv_bfloat16* __restrict__ Bh, const __nv_bfloat16* __restrict__ Bl,
    float* __restrict__ Cm, int K) {
    extern __shared__ __nv_bfloat16 smem[];
    const int bm = blockIdx.y * 128, bn = blockIdx.x * 256;
    if (bm >= d_nvalid_pad) return;
    const int t = threadIdx.x;
    const int warp = t >> 5, lane = t & 31;
    const int wm = warp & 1, wn = warp >> 1;          // 2 x 4 warp grid
    const int mrow0 = wm * 64, nrow0 = wn * 64;       // 64x64 per warp
    const int m4 = lane >> 3, r8 = lane & 7;
    const int mB = (lane >> 3) & 1;

    float acc[4][8][4];
#pragma unroll
    for (int mi = 0; mi < 4; mi++)
#pragma unroll
        for (int ni = 0; ni < 8; ni++)
#pragma unroll
            for (int r = 0; r < 4; r++) acc[mi][ni][r] = 0.f;

    const int KT = K / 32;
    g_load_stage(smem, t, bm, bn, 0, K, Ah, Al, Bh, Bl);
    asm volatile("cp.async.commit_group;\n" ::: "memory");
    g_load_stage(smem + STAGE_ELEMS, t, bm, bn, 32, K, Ah, Al, Bh, Bl);
    asm volatile("cp.async.commit_group;\n" ::: "memory");

    for (int kt = 0; kt < KT; kt++) {
        if (kt + 2 < KT)
            g_load_stage(smem + ((kt + 2) % 3) * STAGE_ELEMS, t, bm, bn, (kt + 2) * 32, K,
                         Ah, Al, Bh, Bl);
        asm volatile("cp.async.commit_group;\n" ::: "memory");
        asm volatile("cp.async.wait_group 2;\n" ::: "memory");
        __syncthreads();

        __nv_bfloat16* st = smem + (kt % 3) * STAGE_ELEMS;
        __nv_bfloat16* sAh = st;
        __nv_bfloat16* sAl = st + TA;
        __nv_bfloat16* sBh = st + 2 * TA;
        __nv_bfloat16* sBl = st + 2 * TA + TB;

#pragma unroll
        for (int ks = 0; ks < 2; ks++) {
            unsigned ah[4][4], al[4][4], bh[8][2], bl[8][2];
#pragma unroll
            for (int mi = 0; mi < 4; mi++) {
                int rr = mrow0 + mi * 16 + (m4 & 1) * 8 + r8;
                int col = (m4 >> 1) * 8 + ks * 16;
                ldsm_x4(ah[mi][0], ah[mi][1], ah[mi][2], ah[mi][3],
                        (unsigned)__cvta_generic_to_shared(&sAh[rr * SKS + col]));
                ldsm_x4(al[mi][0], al[mi][1], al[mi][2], al[mi][3],
                        (unsigned)__cvta_generic_to_shared(&sAl[rr * SKS + col]));
            }
#pragma unroll
            for (int ni = 0; ni < 8; ni++) {
                int rr = nrow0 + ni * 8 + r8;
                int col = mB * 8 + ks * 16;
                ldsm_x2(bh[ni][0], bh[ni][1],
                        (unsigned)__cvta_generic_to_shared(&sBh[rr * SKS + col]));
                ldsm_x2(bl[ni][0], bl[ni][1],
                        (unsigned)__cvta_generic_to_shared(&sBl[rr * SKS + col]));
            }
#pragma unroll
            for (int mi = 0; mi < 4; mi++)
#pragma unroll
                for (int ni = 0; ni < 8; ni++) {
                    mma_bf16(acc[mi][ni], ah[mi], bh[ni]);
                    mma_bf16(acc[mi][ni], ah[mi], bl[ni]);
                    mma_bf16(acc[mi][ni], al[mi], bh[ni]);
                }
        }
        __syncthreads();
    }
#pragma unroll
    for (int mi = 0; mi < 4; mi++) {
        int r0 = bm + mrow0 + mi * 16 + (lane >> 2);
#pragma unroll
        for (int ni = 0; ni < 8; ni++) {
            int c0 = bn + nrow0 + ni * 8 + (lane & 3) * 2;
            *(float2*)&Cm[(size_t)r0 * ND + c0] = make_float2(acc[mi][ni][0], acc[mi][ni][1]);
            *(float2*)&Cm[(size_t)(r0 + 8) * ND + c0] = make_float2(acc[mi][ni][2], acc[mi][ni][3]);
        }
    }
}

// ---------------- CSR gather + fused epilogue (compact rows) --------------
__device__ __forceinline__ unsigned packbf2(__nv_bfloat16 x, __nv_bfloat16 y) {
    return (unsigned)__bfloat16_as_ushort(x) | ((unsigned)__bfloat16_as_ushort(y) << 16);
}

__global__ void __launch_bounds__(128) k_gather1(const float* __restrict__ Y,
                                                 const float* __restrict__ bias,
                                                 const float* __restrict__ bn) {
    int i = blockIdx.x, t = threadIdx.x;
    if (i >= d_nvalid_pad) return;
    int c = t * 4;
    if (i >= d_nvalid) {
        *(uint2*)(d_H1h + (size_t)i * CC + c) = make_uint2(0u, 0u);
        *(uint2*)(d_H1l + (size_t)i * CC + c) = make_uint2(0u, 0u);
        return;
    }
    float4 y0 = *(const float4*)(Y + (size_t)i * ND + c);
    float a0 = y0.x, a1 = y0.y, a2 = y0.z, a3 = y0.w;
    float disv = d_dis[i];
    int e = d_off[i], end = d_off[i + 1];
    for (; e + 1 < end; e += 2) {
        int cu0 = d_adj[e], cu1 = d_adj[e + 1];
        float nr0 = -disv * d_dis[cu0];
        float nr1 = -disv * d_dis[cu1];
        float4 ya = *(const float4*)(Y + (size_t)cu0 * ND + CC + c);
        float4 yb = *(const float4*)(Y + (size_t)cu1 * ND + CC + c);
        a0 += nr0 * ya.x + nr1 * yb.x;
        a1 += nr0 * ya.y + nr1 * yb.y;
        a2 += nr0 * ya.z + nr1 * yb.z;
        a3 += nr0 * ya.w + nr1 * yb.w;
    }
    if (e < end) {
        int cu = d_adj[e];
        float nrm = -disv * d_dis[cu];
        float4 y = *(const float4*)(Y + (size_t)cu * ND + CC + c);
        a0 += nrm * y.x; a1 += nrm * y.y; a2 += nrm * y.z; a3 += nrm * y.w;
    }
    float v[4] = {a0, a1, a2, a3};
    __nv_bfloat16 h[4], l[4];
#pragma unroll
    for (int j = 0; j < 4; j++) {
        float val = v[j] + bias[c + j];
        val = (val - bn[2 * CC + c + j]) * rsqrtf(bn[3 * CC + c + j] + 1e-5f) * bn[c + j]
              + bn[CC + c + j];
        val = fmaxf(val, 0.f);
        bf16split(val, &h[j], &l[j]);
    }
    *(uint2*)(d_H1h + (size_t)i * CC + c) = make_uint2(packbf2(h[0], h[1]), packbf2(h[2], h[3]));
    *(uint2*)(d_H1l + (size_t)i * CC + c) = make_uint2(packbf2(l[0], l[1]), packbf2(l[2], l[3]));
}

__global__ void __launch_bounds__(128) k_gather2(const float* __restrict__ Y,
                                                 const float* __restrict__ bias,
                                                 const float* __restrict__ bn,
                                                 float* __restrict__ H) {
    int i = blockIdx.x, t = threadIdx.x;
    if (i >= d_nvalid) return;
    int c = t * 4;
    float4 y0 = *(const float4*)(Y + (size_t)i * ND + c);
    float a0 = y0.x, a1 = y0.y, a2 = y0.z, a3 = y0.w;
    float disv = d_dis[i];
    int e = d_off[i], end = d_off[i + 1];
    for (; e + 1 < end; e += 2) {
        int cu0 = d_adj[e], cu1 = d_adj[e + 1];
        float nr0 = -disv * d_dis[cu0];
        float nr1 = -disv * d_dis[cu1];
        float4 ya = *(const float4*)(Y + (size_t)cu0 * ND + CC + c);
        float4 yb = *(const float4*)(Y + (size_t)cu1 * ND + CC + c);
        a0 += nr0 * ya.x + nr1 * yb.x;
        a1 += nr0 * ya.y + nr1 * yb.y;
        a2 += nr0 * ya.z + nr1 * yb.z;
        a3 += nr0 * ya.w + nr1 * yb.w;
    }
    if (e < end) {
        int cu = d_adj[e];
        float nrm = -disv * d_dis[cu];
        float4 y = *(const float4*)(Y + (size_t)cu * ND + CC + c);
        a0 += nrm * y.x; a1 += nrm * y.y; a2 += nrm * y.z; a3 += nrm * y.w;
    }
    float v[4] = {a0, a1, a2, a3};
    float o[4];
#pragma unroll
    for (int j = 0; j < 4; j++) {
        float val = v[j] + bias[c + j];
        val = (val - bn[2 * CC + c + j]) * rsqrtf(bn[3 * CC + c + j] + 1e-5f) * bn[c + j]
              + bn[CC + c + j];
        o[j] = fmaxf(val, 0.f);
    }
    *(float4*)(H + (size_t)i * CC + c) = make_float4(o[0], o[1], o[2], o[3]);
}

// per-graph max+mean over valid nodes (H in compact rows)
__global__ void k_pool(const float* __restrict__ H, const int* __restrict__ batch) {
    __shared__ int sb[64];
    __shared__ int scm[64];
    __shared__ unsigned char sv[64];
    int base = blockIdx.x * 64;
    int t = threadIdx.x;
    if (t < 64) {
        int n = base + t;
        sb[t] = batch[n];
        bool val = (d_cluster[n] == n);
        sv[t] = val ? 1 : 0;
        scm[t] = val ? d_cmap[n] : 0;
    }
    __syncthreads();
    int c0 = t, c1 = t + 256;
    float mx0 = 0.f, mx1 = 0.f, s0 = 0.f, s1 = 0.f;
    int cnt = 0, curb = -1;
    for (int i = 0; i < 64; i++) {
        int b = sb[i];
        if (b != curb) {
            if (curb >= 0) {
                atomicMax((unsigned*)&d_gmax[curb * CC + c0], __float_as_uint(mx0));
                atomicMax((unsigned*)&d_gmax[curb * CC + c1], __float_as_uint(mx1));
                atomicAdd(&d_gsum[curb * CC + c0], s0);
                atomicAdd(&d_gsum[curb * CC + c1], s1);
                if (t == 0) atomicAdd(&d_cnt[curb], (float)cnt);
            }
            curb = b; mx0 = mx1 = s0 = s1 = 0.f; cnt = 0;
        }
        if (sv[i]) {
            const float* hr = H + (size_t)scm[i] * CC;
            float h0 = hr[c0], h1 = hr[c1];
            mx0 = fmaxf(mx0, h0); mx1 = fmaxf(mx1, h1);
            s0 += h0; s1 += h1; cnt++;
        }
    }
    if (curb >= 0) {
        atomicMax((unsigned*)&d_gmax[curb * CC + c0], __float_as_uint(mx0));
        atomicMax((unsigned*)&d_gmax[curb * CC + c1], __float_as_uint(mx1));
        atomicAdd(&d_gsum[curb * CC + c0], s0);
        atomicAdd(&d_gsum[curb * CC + c1], s1);
        if (t == 0) atomicAdd(&d_cnt[curb], (float)cnt);
    }
}

__global__ void k_readout(const float* __restrict__ l1w, const float* __restrict__ l1b,
                          const float* __restrict__ l2w, const float* __restrict__ l2b,
                          const float* __restrict__ l3w, const float* __restrict__ l3b,
                          const float* __restrict__ bn3, const float* __restrict__ bn4,
                          float* __restrict__ out) {
    int b = blockIdx.x, t = threadIdx.x;
    __shared__ float g[1024], g1[512], g2[256], zz[4];
    float cn = fmaxf(d_cnt[b], 1.f);
    g[t] = d_gmax[b * CC + t];
    g[CC + t] = d_gsum[b * CC + t] / cn;
    __syncthreads();
    {
        float acc = l1b[t];
        for (int k = 0; k < 1024; k++) acc += g[k] * l1w[k * 512 + t];
        acc = (acc - bn3[1024 + t]) * rsqrtf(bn3[1536 + t] + 1e-5f) * bn3[t] + bn3[512 + t];
        g1[t] = fmaxf(acc, 0.f);
    }
    __syncthreads();
    if (t < 256) {
        float acc = l2b[t];
        for (int k = 0; k < 512; k++) acc += g1[k] * l2w[k * 256 + t];
        acc = (acc - bn4[512 + t]) * rsqrtf(bn4[768 + t] + 1e-5f) * bn4[t] + bn4[256 + t];
        acc = fmaxf(acc, 0.f);
        g2[t] = acc;
        out[32 + b * 256 + t] = acc;
    }
    __syncthreads();
    if (t < 4) {
        float acc = l3b[t];
        for (int k = 0; k < 256; k++) acc += g2[k] * l3w[k * 4 + t];
        zz[t] = fmaxf(acc, 0.f);
    }
    __syncthreads();
    if (t < 4) {
        float m = fmaxf(fmaxf(zz[0], zz[1]), fmaxf(zz[2], zz[3]));
        float s = expf(zz[0] - m) + expf(zz[1] - m) + expf(zz[2] - m) + expf(zz[3] - m);
        out[b * 4 + t] = zz[t] - m - logf(s);
    }
}

extern "C" void kernel_launch(void* const* d_in, const int* in_sizes, int n_in,
                              void* d_out, int out_size) {
    const float* x      = (const float*)d_in[0];
    const int*   ei     = (const int*)d_in[1];
    const int*   batch  = (const int*)d_in[2];
    const float* pool_w = (const float*)d_in[3];
    const float* pool_b = (const float*)d_in[4];
    const float* c1w0   = (const float*)d_in[5];
    const float* c1w1   = (const float*)d_in[6];
    const float* c1b    = (const float*)d_in[7];
    const float* c2w0   = (const float*)d_in[8];
    const float* c2w1   = (const float*)d_in[9];
    const float* c2b    = (const float*)d_in[10];
    const float* bn1    = (const float*)d_in[11];
    const float* bn2    = (const float*)d_in[12];
    const float* bn3    = (const float*)d_in[13];
    const float* bn4    = (const float*)d_in[14];
    const float* l1w    = (const float*)d_in[15];
    const float* l1b    = (const float*)d_in[16];
    const float* l2w    = (const float*)d_in[17];
    const float* l2b    = (const float*)d_in[18];
    const float* l3w    = (const float*)d_in[19];
    const float* l3b    = (const float*)d_in[20];
    float* out = (float*)d_out;

    __nv_bfloat16 *p_Ah, *p_Al, *p_W1h, *p_W1l, *p_W2h, *p_W2l, *p_H1h, *p_H1l;
    float *p_Y, *p_H2;
    cudaGetSymbolAddress((void**)&p_Ah, d_Ah);
    cudaGetSymbolAddress((void**)&p_Al, d_Al);
    cudaGetSymbolAddress((void**)&p_W1h, d_W1h);
    cudaGetSymbolAddress((void**)&p_W1l, d_W1l);
    cudaGetSymbolAddress((void**)&p_W2h, d_W2h);
    cudaGetSymbolAddress((void**)&p_W2l, d_W2l);
    cudaGetSymbolAddress((void**)&p_H1h, d_H1h);
    cudaGetSymbolAddress((void**)&p_H1l, d_H1l);
    cudaGetSymbolAddress((void**)&p_Y, d_Y);
    cudaGetSymbolAddress((void**)&p_H2, d_H2);

    static int init_done = 0;
    static cudaStream_t s1;
    static cudaEvent_t evF1, evJ1, evF2, evJ2;
    if (!init_done) {
        cudaFuncSetAttribute(k_mma_gemm, cudaFuncAttributeMaxDynamicSharedMemorySize, GSMEM);
        cudaStreamCreateWithFlags(&s1, cudaStreamNonBlocking);
        cudaEventCreateWithFlags(&evF1, cudaEventDisableTiming);
        cudaEventCreateWithFlags(&evJ1, cudaEventDisableTiming);
        cudaEventCreateWithFlags(&evF2, cudaEventDisableTiming);
        cudaEventCreateWithFlags(&evJ2, cudaEventDisableTiming);
        init_done = 1;
    }

    // fork: side stream does packw + node_dots while main does init
    cudaEventRecord(evF1, 0);
    cudaStreamWaitEvent(s1, evF1, 0);
    k_init<<<TS / 256, 256>>>();
    k_packw<<<(ND * KP1 + 255) / 256, 256, 0, s1>>>(c1w0, c1w1, c2w0, c2w1);
    k_node_dots<<<NN / 8, 256, 0, s1>>>(x, pool_w);
    cudaEventRecord(evJ1, s1);
    cudaStreamWaitEvent(0, evJ1, 0);

    k_match<<<MBLK, 256>>>(ei, pool_b);
    k_validscan<<<1, 1024>>>();

    // fork: CSR chain on side stream, pxsplit + conv1 GEMM on main
    cudaEventRecord(evF2, 0);
    cudaStreamWaitEvent(s1, evF2, 0);
    k_dedup<<<EE / 256, 256, 0, s1>>>(ei);
    k_scan<<<1, 1024, 0, s1>>>();
    k_csrfill<<<EE / 256, 256, 0, s1>>>();

    k_pxsplit<<<NN, 128>>>(x);
    k_mma_gemm<<<dim3(ND / 256, NN / 128), 256, GSMEM>>>(p_Ah, p_Al, p_W1h, p_W1l, p_Y, KP1);

    cudaEventRecord(evJ2, s1);
    cudaStreamWaitEvent(0, evJ2, 0);

    k_gather1<<<NN, 128>>>(p_Y, c1b, bn1);

    // conv2 (compact rows): [M,512] x [512,1024]
    k_mma_gemm<<<dim3(ND / 256, NN / 128), 256, GSMEM>>>(p_H1h, p_H1l, p_W2h, p_W2l, p_Y, CC);
    k_gather2<<<NN, 128>>>(p_Y, c2b, bn2, p_H2);

    // pooling + readout
    k_pool<<<NN / 64, 256>>>(p_H2, batch);
    k_readout<<<BB, 512>>>(l1w, l1b, l2w, l2b, l3w, l3b, bn3, bn4, out);
}